// round 2
// baseline (speedup 1.0000x reference)
#include <cuda_runtime.h>
#include <math.h>
#include <stdint.h>

#define B_  8
#define C_  512
#define DD_ 256
#define HW_ 4096
#define HEADS_ 8
#define CPH_ 32
#define HID_ 16

// ---------------- scratch (static device globals; no allocation) ----------------
__device__ float  g_wt[9*512*256];          // conv weights transposed [tap][cin][co]
__device__ float  g_pwt[512*512];           // proj weights transposed [c][o]
__device__ float2 g_twid[4096];             // e^{-2*pi*i*k/4096}, FULL circle
__device__ float  g_y   [(size_t)B_*DD_*HW_];   // conv+bn+relu output
__device__ float  g_fre [(size_t)B_*DD_*HW_];   // fft2 real
__device__ float  g_fim [(size_t)B_*DD_*HW_];   // fft2 imag
__device__ float  g_gfre[(size_t)B_*DD_*HW_];   // gate*f real
__device__ float  g_gfim[(size_t)B_*DD_*HW_];   // gate*f imag
__device__ float  g_g1  [(size_t)B_*HID_*HW_];
__device__ float  g_invn[B_*DD_];
__device__ float  g_attnS[4*64*1024*2];     // partial attn sums [nq][bh][pair][re,im]
__device__ float2 g_attn2[64*1024];         // softmaxed + ifft32-folded attn
__device__ float  g_out2[(size_t)B_*C_*HW_];    // concat(out_f2,out_l2)+x2d

// ---------------- prep: twiddles + weight transposes ----------------
__global__ void prep_kernel(const float* __restrict__ cw, const float* __restrict__ pw) {
    int tid = blockIdx.x*blockDim.x + threadIdx.x;
    int stride = gridDim.x*blockDim.x;
    if (tid < 4096) {
        float s, c;
        sincosf(-6.28318530717958647692f * (float)tid / 4096.f, &s, &c);
        g_twid[tid] = make_float2(c, s);
    }
    for (int e = tid; e < 9*512*256; e += stride) {
        int co = e / (512*9);
        int rem = e - co*512*9;
        int cin = rem / 9;
        int t = rem - cin*9;
        g_wt[(t*512 + cin)*256 + co] = cw[e];
    }
    for (int e = tid; e < 512*512; e += stride) {
        int o = e >> 9, c = e & 511;
        g_pwt[c*512 + o] = pw[e];
    }
}

// ---------------- conv (dilated 3x3, 512->256) + bias + BN + ReLU ----------------
// grid: (4 co-tiles, 64 rows, 8 batch), 256 threads, 64 pos x 64 co tile, 4x4 micro
__global__ void conv_kernel(const float* __restrict__ x, const float* __restrict__ cb,
                            const float* __restrict__ bg, const float* __restrict__ bb,
                            const float* __restrict__ bm, const float* __restrict__ bv) {
    __shared__ float xs[32*68];
    __shared__ float ws[32*68];
    int b = blockIdx.z, ph = blockIdx.y, cot = blockIdx.x;
    int tid = threadIdx.x;
    int tx = tid & 15, ty = tid >> 4;
    float acc[4][4];
#pragma unroll
    for (int i = 0; i < 4; i++)
#pragma unroll
        for (int j = 0; j < 4; j++) acc[i][j] = 0.f;

    for (int tap = 0; tap < 9; tap++) {
        int kh = tap / 3, kw = tap - kh*3;
        int ih = ph + 3*(kh - 1);
        bool vh = ((unsigned)ih < 64u);
        int sh = 3*(kw - 1);
        const float* wtp = g_wt + (size_t)tap*512*256;
        for (int kc = 0; kc < 512; kc += 32) {
            __syncthreads();
            // xs[k][pos]
#pragma unroll
            for (int e0 = 0; e0 < 2048; e0 += 256) {
                int e = e0 + tid;
                int k = e & 31, pos = e >> 5;
                int iw = pos + sh;
                float v = 0.f;
                if (vh && (unsigned)iw < 64u)
                    v = x[(((size_t)b*HW_) + (size_t)(ih*64 + iw))*C_ + kc + k];
                xs[k*68 + pos] = v;
            }
            // ws[k][co]
#pragma unroll
            for (int e0 = 0; e0 < 2048; e0 += 256) {
                int e = e0 + tid;
                int k = e >> 6, co = e & 63;
                ws[k*68 + co] = wtp[(size_t)(kc + k)*256 + cot*64 + co];
            }
            __syncthreads();
#pragma unroll
            for (int k = 0; k < 32; k++) {
                float4 xv = *(const float4*)&xs[k*68 + ty*4];
                float4 wv = *(const float4*)&ws[k*68 + tx*4];
                acc[0][0] += xv.x*wv.x; acc[0][1] += xv.x*wv.y; acc[0][2] += xv.x*wv.z; acc[0][3] += xv.x*wv.w;
                acc[1][0] += xv.y*wv.x; acc[1][1] += xv.y*wv.y; acc[1][2] += xv.y*wv.z; acc[1][3] += xv.y*wv.w;
                acc[2][0] += xv.z*wv.x; acc[2][1] += xv.z*wv.y; acc[2][2] += xv.z*wv.z; acc[2][3] += xv.z*wv.w;
                acc[3][0] += xv.w*wv.x; acc[3][1] += xv.w*wv.y; acc[3][2] += xv.w*wv.z; acc[3][3] += xv.w*wv.w;
            }
        }
    }
    int co0 = cot*64 + tx*4;
    int posb = ty*4;
#pragma unroll
    for (int j = 0; j < 4; j++) {
        int o = co0 + j;
        float s = bg[o] * rsqrtf(bv[o] + 1e-5f);
        float t0 = cb[o]*s + bb[o] - bm[o]*s;
#pragma unroll
        for (int i = 0; i < 4; i++) {
            float v = fmaxf(acc[i][j]*s + t0, 0.f);
            g_y[((size_t)(b*DD_ + o))*HW_ + ph*64 + posb + i] = v;
        }
    }
}

// ---------------- 64x64 2D FFT core (shared memory, radix-2) ----------------
__device__ __forceinline__ void fft64_2d(float* sr, float* si, int tid, float sign) {
    // FFT along rows (w); data pre-bit-reversed along w
    for (int s = 1; s <= 6; s++) {
        int hm = 1 << (s-1);
        int tw = 4096 >> s;
        __syncthreads();
        for (int t = tid; t < 2048; t += 256) {
            int j = t >> 6, r = t & 63;
            int pos = j & (hm-1);
            int base = r*65 + (((j >> (s-1)) << s) | pos);
            float2 w = g_twid[pos*tw];
            float wr = w.x, wi = sign*w.y;
            int i2 = base + hm;
            float br = sr[i2], bi = si[i2];
            float tr = br*wr - bi*wi, ti = br*wi + bi*wr;
            float ar = sr[base], ai = si[base];
            sr[base] = ar + tr; si[base] = ai + ti;
            sr[i2]   = ar - tr; si[i2]   = ai - ti;
        }
    }
    // bit-reverse permute along rows (h) for column pass
    __syncthreads();
    for (int e = tid; e < 4096; e += 256) {
        int r = e >> 6, cc = e & 63;
        int br = __brev(r) >> 26;
        if (r < br) {
            float a = sr[r*65+cc]; sr[r*65+cc] = sr[br*65+cc]; sr[br*65+cc] = a;
            float b = si[r*65+cc]; si[r*65+cc] = si[br*65+cc]; si[br*65+cc] = b;
        }
    }
    // FFT along columns (h)
    for (int s = 1; s <= 6; s++) {
        int hm = 1 << (s-1);
        int tw = 4096 >> s;
        __syncthreads();
        for (int t = tid; t < 2048; t += 256) {
            int j = t >> 6, cc = t & 63;
            int pos = j & (hm-1);
            int rowb = ((j >> (s-1)) << s) | pos;
            int base = rowb*65 + cc;
            int i2 = base + hm*65;
            float2 w = g_twid[pos*tw];
            float wr = w.x, wi = sign*w.y;
            float br = sr[i2], bi = si[i2];
            float tr = br*wr - bi*wi, ti = br*wi + bi*wr;
            float ar = sr[base], ai = si[base];
            sr[base] = ar + tr; si[base] = ai + ti;
            sr[i2]   = ar - tr; si[i2]   = ai - ti;
        }
    }
    __syncthreads();
}

// forward fft2 of conv output (real input)
__global__ void fft2_fwd_kernel() {
    __shared__ float sr[64*65], si[64*65];
    int bc = blockIdx.x;
    int tid = threadIdx.x;
    const float* src = g_y + (size_t)bc*HW_;
    for (int e = tid; e < 4096; e += 256) {
        int r = e >> 6, w = e & 63;
        int bw = __brev(w) >> 26;
        sr[r*65 + bw] = src[e];
        si[r*65 + bw] = 0.f;
    }
    fft64_2d(sr, si, tid, 1.f);
    float* dr = g_fre + (size_t)bc*HW_;
    float* di = g_fim + (size_t)bc*HW_;
    for (int e = tid; e < 4096; e += 256) {
        dr[e] = sr[(e>>6)*65 + (e&63)];
        di[e] = si[(e>>6)*65 + (e&63)];
    }
}

// inverse fft2 of gate*f, abs, +x, write upper half of out2
__global__ void ifft2_kernel(const float* __restrict__ x) {
    __shared__ float sr[64*65], si[64*65];
    int bc = blockIdx.x;            // b*256 + c
    int b = bc >> 8, c = bc & 255;
    int tid = threadIdx.x;
    const float* srcr = g_gfre + (size_t)bc*HW_;
    const float* srci = g_gfim + (size_t)bc*HW_;
    for (int e = tid; e < 4096; e += 256) {
        int r = e >> 6, w = e & 63;
        int bw = __brev(w) >> 26;
        sr[r*65 + bw] = srcr[e];
        si[r*65 + bw] = srci[e];
    }
    fft64_2d(sr, si, tid, -1.f);
    for (int e = tid; e < 4096; e += 256) {
        float re = sr[(e>>6)*65 + (e&63)], im = si[(e>>6)*65 + (e&63)];
        float v = sqrtf(re*re + im*im) * (1.f/4096.f)
                + x[((size_t)b*HW_ + e)*C_ + (256 + c)];
        g_out2[((size_t)(b*512 + 256 + c))*HW_ + e] = v;
    }
}

// ---------------- L2 norms of f rows ----------------
__global__ void norms_kernel() {
    int bc = blockIdx.x;
    int tid = threadIdx.x;
    const float* fr = g_fre + (size_t)bc*HW_;
    const float* fi = g_fim + (size_t)bc*HW_;
    float s = 0.f;
    for (int i = tid; i < HW_; i += 256) {
        float a = fr[i], b = fi[i];
        s += a*a + b*b;
    }
    for (int o = 16; o; o >>= 1) s += __shfl_xor_sync(0xffffffffu, s, o);
    __shared__ float red[8];
    if ((tid & 31) == 0) red[tid>>5] = s;
    __syncthreads();
    if (tid < 8) {
        float v = red[tid];
        for (int o = 4; o; o >>= 1) v += __shfl_xor_sync(0xffu, v, o);
        if (tid == 0) g_invn[bc] = 1.f / fmaxf(sqrtf(v), 1e-12f);
    }
}

// ---------------- attn partial GEMM: S[c][d] = sum_n f_c f_d (complex, no conj) ----
// grid 256: blockIdx = bh*4 + nq (quarter of n)
__global__ void attn_gemm_kernel() {
    int bh = blockIdx.x >> 2, nq = blockIdx.x & 3;
    int tid = threadIdx.x;
    __shared__ float sre[32*65], sim[32*65];
    const float* fr = g_fre + (size_t)bh*CPH_*HW_ + nq*1024;
    const float* fi = g_fim + (size_t)bh*CPH_*HW_ + nq*1024;
    int p0 = tid*4;
    int c = p0 >> 5, d0 = p0 & 31;
    float ar[4] = {0,0,0,0}, ai[4] = {0,0,0,0};
    for (int n0 = 0; n0 < 1024; n0 += 64) {
        __syncthreads();
        for (int e = tid; e < 2048; e += 256) {
            int cc = e >> 6, nn = e & 63;
            sre[cc*65+nn] = fr[(size_t)cc*HW_ + n0 + nn];
            sim[cc*65+nn] = fi[(size_t)cc*HW_ + n0 + nn];
        }
        __syncthreads();
        for (int nn = 0; nn < 64; nn++) {
            float cr = sre[c*65+nn], ci = sim[c*65+nn];
#pragma unroll
            for (int q = 0; q < 4; q++) {
                float dr = sre[(d0+q)*65+nn], di = sim[(d0+q)*65+nn];
                ar[q] += cr*dr - ci*di;
                ai[q] += cr*di + ci*dr;
            }
        }
    }
    float* dst = g_attnS + ((size_t)(nq*64 + bh)*1024 + p0)*2;
#pragma unroll
    for (int q = 0; q < 4; q++) { dst[q*2] = ar[q]; dst[q*2+1] = ai[q]; }
}

// ---------------- attn finalize: scale, softmax(re)/softmax(im), ifft32 fold ------
__global__ void attn_fin_kernel(const float* __restrict__ temp) {
    int bh = blockIdx.x;
    int head = bh & 7;
    int tid = threadIdx.x;
    __shared__ float ar_[32*33], ai_[32*33];
    float tmp = temp[head];
    for (int p = tid; p < 1024; p += 256) {
        int cc = p >> 5, dd = p & 31;
        float sr = 0.f, si = 0.f;
#pragma unroll
        for (int q = 0; q < 4; q++) {
            const float* src = g_attnS + ((size_t)(q*64 + bh)*1024 + p)*2;
            sr += src[0]; si += src[1];
        }
        float sc = g_invn[bh*32 + cc] * g_invn[bh*32 + dd] * tmp;
        ar_[cc*33+dd] = sr*sc;
        ai_[cc*33+dd] = si*sc;
    }
    __syncthreads();
    int w = tid >> 5, lane = tid & 31;
    for (int r = w; r < 32; r += 8) {
        float vr = ar_[r*33+lane];
        float m = vr;
        for (int o = 16; o; o >>= 1) m = fmaxf(m, __shfl_xor_sync(0xffffffffu, m, o));
        float e = expf(vr - m); float s = e;
        for (int o = 16; o; o >>= 1) s += __shfl_xor_sync(0xffffffffu, s, o);
        ar_[r*33+lane] = e / s;
        float vi = ai_[r*33+lane];
        m = vi;
        for (int o = 16; o; o >>= 1) m = fmaxf(m, __shfl_xor_sync(0xffffffffu, m, o));
        e = expf(vi - m); s = e;
        for (int o = 16; o; o >>= 1) s += __shfl_xor_sync(0xffffffffu, s, o);
        ai_[r*33+lane] = e / s;
    }
    __syncthreads();
    // attn2[k][d] = (1/32) sum_c e^{+2*pi*i*k*c/32} attn[c][d]
    for (int p = tid; p < 1024; p += 256) {
        int k = p >> 5, dd = p & 31;
        float accr = 0.f, acci = 0.f;
#pragma unroll
        for (int cc = 0; cc < 32; cc++) {
            float2 w2 = g_twid[((k*cc) & 31) * 128];   // full-circle table now
            float wr = w2.x, wi = -w2.y;   // conj -> e^{+i theta}
            float xr = ar_[cc*33+dd], xi = ai_[cc*33+dd];
            accr += wr*xr - wi*xi;
            acci += wr*xi + wi*xr;
        }
        g_attn2[(size_t)bh*1024 + p] = make_float2(accr*(1.f/32.f), acci*(1.f/32.f));
    }
}

// ---------------- out row: attn2 @ f, ifft4096, abs, +x, write lower out2 ---------
#define SKW(i) ((i) + ((i) >> 7))
__global__ void outrow_kernel(const float* __restrict__ x) {
    __shared__ float sr[4128], si[4128];
    __shared__ float2 a2[32];
    int gid = blockIdx.x;          // b*256 + head*32 + k
    int bh = gid >> 5, k = gid & 31;
    int b = gid >> 8, cg = gid & 255;
    int tid = threadIdx.x;
    if (tid < 32) a2[tid] = g_attn2[(size_t)bh*1024 + k*32 + tid];
    __syncthreads();
    const float* fr = g_fre + (size_t)bh*CPH_*HW_;
    const float* fi = g_fim + (size_t)bh*CPH_*HW_;
    for (int nn = tid; nn < 4096; nn += 256) {
        float accr = 0.f, acci = 0.f;
#pragma unroll
        for (int d = 0; d < 32; d++) {
            float frv = fr[(size_t)d*HW_ + nn], fiv = fi[(size_t)d*HW_ + nn];
            float2 a = a2[d];
            accr += a.x*frv - a.y*fiv;
            acci += a.x*fiv + a.y*frv;
        }
        int rb = __brev(nn) >> 20;
        sr[SKW(rb)] = accr;
        si[SKW(rb)] = acci;
    }
    for (int s = 1; s <= 12; s++) {
        int hm = 1 << (s-1);
        int tw = 4096 >> s;
        __syncthreads();
        for (int t = tid; t < 2048; t += 256) {
            int pos = t & (hm-1);
            int base = ((t >> (s-1)) << s) | pos;
            float2 w = g_twid[pos*tw];
            float wr = w.x, wi = -w.y;   // inverse
            int i1 = SKW(base), i2 = SKW(base+hm);
            float br = sr[i2], bi = si[i2];
            float tr = br*wr - bi*wi, ti = br*wi + bi*wr;
            float a0 = sr[i1], a1 = si[i1];
            sr[i1] = a0 + tr; si[i1] = a1 + ti;
            sr[i2] = a0 - tr; si[i2] = a1 - ti;
        }
    }
    __syncthreads();
    for (int nn = tid; nn < 4096; nn += 256) {
        float re = sr[SKW(nn)], im = si[SKW(nn)];
        float v = sqrtf(re*re + im*im) * (1.f/4096.f)
                + x[((size_t)b*HW_ + nn)*C_ + cg];
        g_out2[((size_t)(b*512) + cg)*HW_ + nn] = v;
    }
}

// ---------------- gating MLP: g1 = relu(bn(w1 @ f.real)) ----------------
__global__ void g1_kernel(const float* __restrict__ w1w, const float* __restrict__ w1b,
                          const float* __restrict__ bg, const float* __restrict__ bb,
                          const float* __restrict__ bm, const float* __restrict__ bv) {
    __shared__ float sw[HID_*DD_];
    __shared__ float sa[HID_], st[HID_];
    int b = blockIdx.y;
    int tid = threadIdx.x;
    int n = blockIdx.x*256 + tid;
    for (int e = tid; e < HID_*DD_; e += 256) sw[e] = w1w[e];
    if (tid < HID_) {
        float s = bg[tid] * rsqrtf(bv[tid] + 1e-5f);
        sa[tid] = s;
        st[tid] = w1b[tid]*s + bb[tid] - bm[tid]*s;
    }
    __syncthreads();
    float acc[HID_];
#pragma unroll
    for (int o = 0; o < HID_; o++) acc[o] = 0.f;
    const float* fr = g_fre + (size_t)b*DD_*HW_ + n;
    for (int c = 0; c < DD_; c++) {
        float v = fr[(size_t)c*HW_];
#pragma unroll
        for (int o = 0; o < HID_; o++) acc[o] += v * sw[o*DD_ + c];
    }
#pragma unroll
    for (int o = 0; o < HID_; o++)
        g_g1[((size_t)(b*HID_ + o))*HW_ + n] = fmaxf(acc[o]*sa[o] + st[o], 0.f);
}

// gate = sigmoid(w2 @ g1 + b); gf = gate * f
__global__ void gate_kernel(const float* __restrict__ w2w, const float* __restrict__ w2b) {
    __shared__ float sw[DD_*HID_];
    __shared__ float sb[DD_];
    int b = blockIdx.y;
    int tid = threadIdx.x;
    int n = blockIdx.x*256 + tid;
    for (int e = tid; e < DD_*HID_; e += 256) sw[e] = w2w[e];
    if (tid < DD_) sb[tid] = w2b[tid];
    __syncthreads();
    float gv[HID_];
#pragma unroll
    for (int o = 0; o < HID_; o++) gv[o] = g_g1[((size_t)(b*HID_ + o))*HW_ + n];
    for (int co = 0; co < DD_; co++) {
        float a = sb[co];
#pragma unroll
        for (int o = 0; o < HID_; o++) a += sw[co*HID_ + o] * gv[o];
        float gt = 1.f / (1.f + expf(-a));
        size_t idx = ((size_t)(b*DD_ + co))*HW_ + n;
        g_gfre[idx] = gt * g_fre[idx];
        g_gfim[idx] = gt * g_fim[idx];
    }
}

// ---------------- final projection: out[b][n][o] = proj_w @ out2 + proj_b ---------
__global__ void proj_kernel(const float* __restrict__ pb, float* __restrict__ out) {
    __shared__ float as_[32*68], ws_[32*68];
    int b = blockIdx.z;
    int n0 = blockIdx.x*64, o0 = blockIdx.y*64;
    int tid = threadIdx.x;
    int tx = tid & 15, ty = tid >> 4;
    float acc[4][4];
#pragma unroll
    for (int i = 0; i < 4; i++)
#pragma unroll
        for (int j = 0; j < 4; j++) acc[i][j] = 0.f;
    for (int kc = 0; kc < 512; kc += 32) {
        __syncthreads();
        for (int e = tid; e < 2048; e += 256) {
            int k = e >> 6, nn = e & 63;
            as_[k*68 + nn] = g_out2[((size_t)(b*512 + kc + k))*HW_ + n0 + nn];
            ws_[k*68 + nn] = g_pwt[(size_t)(kc + k)*512 + o0 + nn];
        }
        __syncthreads();
#pragma unroll
        for (int k = 0; k < 32; k++) {
            float4 xv = *(const float4*)&as_[k*68 + ty*4];
            float4 wv = *(const float4*)&ws_[k*68 + tx*4];
            acc[0][0] += xv.x*wv.x; acc[0][1] += xv.x*wv.y; acc[0][2] += xv.x*wv.z; acc[0][3] += xv.x*wv.w;
            acc[1][0] += xv.y*wv.x; acc[1][1] += xv.y*wv.y; acc[1][2] += xv.y*wv.z; acc[1][3] += xv.y*wv.w;
            acc[2][0] += xv.z*wv.x; acc[2][1] += xv.z*wv.y; acc[2][2] += xv.z*wv.z; acc[2][3] += xv.z*wv.w;
            acc[3][0] += xv.w*wv.x; acc[3][1] += xv.w*wv.y; acc[3][2] += xv.w*wv.z; acc[3][3] += xv.w*wv.w;
        }
    }
    int o = o0 + tx*4;
    float b0 = pb[o], b1 = pb[o+1], b2 = pb[o+2], b3 = pb[o+3];
#pragma unroll
    for (int i = 0; i < 4; i++) {
        int n = n0 + ty*4 + i;
        float4 v = make_float4(acc[i][0]+b0, acc[i][1]+b1, acc[i][2]+b2, acc[i][3]+b3);
        *(float4*)&out[((size_t)b*HW_ + n)*C_ + o] = v;
    }
}

// ---------------- launch ----------------
extern "C" void kernel_launch(void* const* d_in, const int* in_sizes, int n_in,
                              void* d_out, int out_size) {
    const float* x       = (const float*)d_in[0];
    const float* conv2_w = (const float*)d_in[1];
    const float* conv2_b = (const float*)d_in[2];
    const float* bn2_g   = (const float*)d_in[3];
    const float* bn2_b   = (const float*)d_in[4];
    const float* bn2_m   = (const float*)d_in[5];
    const float* bn2_v   = (const float*)d_in[6];
    const float* temp    = (const float*)d_in[7];
    const float* w1_w    = (const float*)d_in[8];
    const float* w1_b    = (const float*)d_in[9];
    const float* bnw_g   = (const float*)d_in[10];
    const float* bnw_b   = (const float*)d_in[11];
    const float* bnw_m   = (const float*)d_in[12];
    const float* bnw_v   = (const float*)d_in[13];
    const float* w2_w    = (const float*)d_in[14];
    const float* w2_b    = (const float*)d_in[15];
    const float* proj_w  = (const float*)d_in[16];
    const float* proj_b  = (const float*)d_in[17];
    float* out = (float*)d_out;

    prep_kernel<<<1024, 256>>>(conv2_w, proj_w);
    conv_kernel<<<dim3(4, 64, 8), 256>>>(x, conv2_b, bn2_g, bn2_b, bn2_m, bn2_v);
    fft2_fwd_kernel<<<2048, 256>>>();
    norms_kernel<<<2048, 256>>>();
    attn_gemm_kernel<<<256, 256>>>();
    attn_fin_kernel<<<64, 256>>>(temp);
    outrow_kernel<<<2048, 256>>>(x);
    g1_kernel<<<dim3(16, 8), 256>>>(w1_w, w1_b, bnw_g, bnw_b, bnw_m, bnw_v);
    gate_kernel<<<dim3(16, 8), 256>>>(w2_w, w2_b);
    ifft2_kernel<<<2048, 256>>>(x);
    proj_kernel<<<dim3(64, 8, 8), 256>>>(proj_b, out);
}

// round 3
// speedup vs baseline: 1.8092x; 1.8092x over previous
#include <cuda_runtime.h>
#include <math.h>
#include <stdint.h>

#define B_  8
#define C_  512
#define DD_ 256
#define HW_ 4096
#define HEADS_ 8
#define CPH_ 32
#define HID_ 16

// ---------------- scratch (static device globals; no allocation) ----------------
__device__ float  g_wt[9*256*512];          // conv weights [tap][co][cin]
__device__ float2 g_twid[4096];             // e^{-2*pi*i*k/4096}, FULL circle
__device__ float  g_y   [(size_t)B_*DD_*HW_];   // conv+bn+relu output
__device__ float  g_fre [(size_t)B_*DD_*HW_];   // fft2 real
__device__ float  g_fim [(size_t)B_*DD_*HW_];   // fft2 imag
__device__ float  g_gfre[(size_t)B_*DD_*HW_];   // gate*f real
__device__ float  g_gfim[(size_t)B_*DD_*HW_];   // gate*f imag
__device__ float  g_g1  [(size_t)B_*HID_*HW_];
__device__ float  g_invn[B_*DD_];
__device__ float  g_attnS[4*64*1024*2];     // partial attn sums [nq][bh][pair][re,im]
__device__ float2 g_attn2[64*1024];         // softmaxed + ifft32-folded attn
__device__ float  g_out2[(size_t)B_*C_*HW_];    // concat(out_f2,out_l2)+x2d

// ---------------- tf32 helpers ----------------
__device__ __forceinline__ uint32_t f2tf(float f) {
    uint32_t u;
    asm("cvt.rna.tf32.f32 %0, %1;" : "=r"(u) : "f"(f));
    return u;
}
__device__ __forceinline__ void mma8(float c[4], const uint32_t a[4], uint32_t b0, uint32_t b1) {
    asm volatile("mma.sync.aligned.m16n8k8.row.col.f32.tf32.tf32.f32 "
        "{%0,%1,%2,%3}, {%4,%5,%6,%7}, {%8,%9}, {%0,%1,%2,%3};"
        : "+f"(c[0]), "+f"(c[1]), "+f"(c[2]), "+f"(c[3])
        : "r"(a[0]), "r"(a[1]), "r"(a[2]), "r"(a[3]), "r"(b0), "r"(b1));
}

// ---------------- prep: twiddles + conv weight transpose ----------------
__global__ void prep_kernel(const float* __restrict__ cw) {
    int tid = blockIdx.x*blockDim.x + threadIdx.x;
    int stride = gridDim.x*blockDim.x;
    if (tid < 4096) {
        float s, c;
        sincosf(-6.28318530717958647692f * (float)tid / 4096.f, &s, &c);
        g_twid[tid] = make_float2(c, s);
    }
    for (int e = tid; e < 9*256*512; e += stride) {
        int tap = e / (256*512);
        int rem = e - tap*256*512;
        int co = rem >> 9;
        int cin = rem & 511;
        g_wt[e] = cw[(co*512 + cin)*9 + tap];
    }
}

// ---------------- conv via tf32 mma: 128co x 128pos tiles ----------------
// grid (2 co-tiles, 32 pos-tiles, 8 b), 256 threads = 8 warps (4 m x 2 n)
__global__ void conv_mma_kernel(const float* __restrict__ x, const float* __restrict__ cb,
                                const float* __restrict__ bg, const float* __restrict__ bb,
                                const float* __restrict__ bm, const float* __restrict__ bv) {
    __shared__ uint32_t xs[128][20];   // [pos][k], pad 20
    __shared__ uint32_t ws[128][20];   // [co ][k]
    int b = blockIdx.z, pt = blockIdx.y, ct = blockIdx.x;
    int tid = threadIdx.x, lane = tid & 31, warp = tid >> 5;
    int wm = warp & 3, wn = warp >> 2;
    int g = lane >> 2, t = lane & 3;
    float acc[2][8][4];
#pragma unroll
    for (int i = 0; i < 2; i++)
#pragma unroll
        for (int j = 0; j < 8; j++)
#pragma unroll
            for (int q = 0; q < 4; q++) acc[i][j][q] = 0.f;

    int pos0 = pt*128;
    for (int tap = 0; tap < 9; tap++) {
        int dh = 3*((tap/3) - 1), dw = 3*((tap%3) - 1);
        const float* wtp = g_wt + ((size_t)tap*256 + ct*128)*512;
        for (int kc = 0; kc < 512; kc += 16) {
            __syncthreads();
#pragma unroll
            for (int r = 0; r < 2; r++) {
                int e = tid + r*256;
                int pos = e >> 2, ch = e & 3;
                int gp = pos0 + pos;
                int ih = (gp >> 6) + dh, iw = (gp & 63) + dw;
                float4 v = make_float4(0.f, 0.f, 0.f, 0.f);
                if ((unsigned)ih < 64u && (unsigned)iw < 64u)
                    v = *(const float4*)&x[((size_t)(b*HW_) + ih*64 + iw)*C_ + kc + ch*4];
                uint4 u = make_uint4(f2tf(v.x), f2tf(v.y), f2tf(v.z), f2tf(v.w));
                *(uint4*)&xs[pos][ch*4] = u;
            }
#pragma unroll
            for (int r = 0; r < 2; r++) {
                int e = tid + r*256;
                int co = e >> 2, ch = e & 3;
                float4 v = *(const float4*)&wtp[(size_t)co*512 + kc + ch*4];
                uint4 u = make_uint4(f2tf(v.x), f2tf(v.y), f2tf(v.z), f2tf(v.w));
                *(uint4*)&ws[co][ch*4] = u;
            }
            __syncthreads();
#pragma unroll
            for (int ks = 0; ks < 16; ks += 8) {
                int kr = ks + t;
                uint32_t a[2][4];
#pragma unroll
                for (int mi = 0; mi < 2; mi++) {
                    int m0 = wm*32 + mi*16 + g;
                    a[mi][0] = ws[m0][kr];
                    a[mi][1] = ws[m0+8][kr];
                    a[mi][2] = ws[m0][kr+4];
                    a[mi][3] = ws[m0+8][kr+4];
                }
#pragma unroll
                for (int ni = 0; ni < 8; ni++) {
                    int n0 = wn*64 + ni*8 + g;
                    uint32_t b0 = xs[n0][kr];
                    uint32_t b1 = xs[n0][kr+4];
                    mma8(acc[0][ni], a[0], b0, b1);
                    mma8(acc[1][ni], a[1], b0, b1);
                }
            }
        }
    }
    // epilogue: BN + ReLU, write g_y[b][co][pos]
#pragma unroll
    for (int mi = 0; mi < 2; mi++) {
#pragma unroll
        for (int half = 0; half < 2; half++) {
            int o = ct*128 + wm*32 + mi*16 + g + half*8;
            float s = bg[o] * rsqrtf(bv[o] + 1e-5f);
            float t0 = cb[o]*s + bb[o] - bm[o]*s;
            float* dst = g_y + ((size_t)(b*DD_ + o))*HW_;
#pragma unroll
            for (int ni = 0; ni < 8; ni++) {
                int pos = pos0 + wn*64 + ni*8 + 2*t;
                float v0 = fmaxf(acc[mi][ni][half*2+0]*s + t0, 0.f);
                float v1 = fmaxf(acc[mi][ni][half*2+1]*s + t0, 0.f);
                *(float2*)&dst[pos] = make_float2(v0, v1);
            }
        }
    }
}

// ---------------- 64x64 2D FFT core (shared memory, radix-2) ----------------
__device__ __forceinline__ void fft64_2d(float* sr, float* si, int tid, float sign) {
    for (int s = 1; s <= 6; s++) {
        int hm = 1 << (s-1);
        int tw = 4096 >> s;
        __syncthreads();
        for (int t = tid; t < 2048; t += 256) {
            int j = t >> 6, r = t & 63;
            int pos = j & (hm-1);
            int base = r*65 + (((j >> (s-1)) << s) | pos);
            float2 w = g_twid[pos*tw];
            float wr = w.x, wi = sign*w.y;
            int i2 = base + hm;
            float br = sr[i2], bi = si[i2];
            float tr = br*wr - bi*wi, ti = br*wi + bi*wr;
            float ar = sr[base], ai = si[base];
            sr[base] = ar + tr; si[base] = ai + ti;
            sr[i2]   = ar - tr; si[i2]   = ai - ti;
        }
    }
    __syncthreads();
    for (int e = tid; e < 4096; e += 256) {
        int r = e >> 6, cc = e & 63;
        int br = __brev(r) >> 26;
        if (r < br) {
            float a = sr[r*65+cc]; sr[r*65+cc] = sr[br*65+cc]; sr[br*65+cc] = a;
            float b = si[r*65+cc]; si[r*65+cc] = si[br*65+cc]; si[br*65+cc] = b;
        }
    }
    for (int s = 1; s <= 6; s++) {
        int hm = 1 << (s-1);
        int tw = 4096 >> s;
        __syncthreads();
        for (int t = tid; t < 2048; t += 256) {
            int j = t >> 6, cc = t & 63;
            int pos = j & (hm-1);
            int rowb = ((j >> (s-1)) << s) | pos;
            int base = rowb*65 + cc;
            int i2 = base + hm*65;
            float2 w = g_twid[pos*tw];
            float wr = w.x, wi = sign*w.y;
            float br = sr[i2], bi = si[i2];
            float tr = br*wr - bi*wi, ti = br*wi + bi*wr;
            float ar = sr[base], ai = si[base];
            sr[base] = ar + tr; si[base] = ai + ti;
            sr[i2]   = ar - tr; si[i2]   = ai - ti;
        }
    }
    __syncthreads();
}

__global__ void fft2_fwd_kernel() {
    __shared__ float sr[64*65], si[64*65];
    int bc = blockIdx.x;
    int tid = threadIdx.x;
    const float* src = g_y + (size_t)bc*HW_;
    for (int e = tid; e < 4096; e += 256) {
        int r = e >> 6, w = e & 63;
        int bw = __brev(w) >> 26;
        sr[r*65 + bw] = src[e];
        si[r*65 + bw] = 0.f;
    }
    fft64_2d(sr, si, tid, 1.f);
    float* dr = g_fre + (size_t)bc*HW_;
    float* di = g_fim + (size_t)bc*HW_;
    for (int e = tid; e < 4096; e += 256) {
        dr[e] = sr[(e>>6)*65 + (e&63)];
        di[e] = si[(e>>6)*65 + (e&63)];
    }
}

__global__ void ifft2_kernel(const float* __restrict__ x) {
    __shared__ float sr[64*65], si[64*65];
    int bc = blockIdx.x;
    int b = bc >> 8, c = bc & 255;
    int tid = threadIdx.x;
    const float* srcr = g_gfre + (size_t)bc*HW_;
    const float* srci = g_gfim + (size_t)bc*HW_;
    for (int e = tid; e < 4096; e += 256) {
        int r = e >> 6, w = e & 63;
        int bw = __brev(w) >> 26;
        sr[r*65 + bw] = srcr[e];
        si[r*65 + bw] = srci[e];
    }
    fft64_2d(sr, si, tid, -1.f);
    for (int e = tid; e < 4096; e += 256) {
        float re = sr[(e>>6)*65 + (e&63)], im = si[(e>>6)*65 + (e&63)];
        float v = sqrtf(re*re + im*im) * (1.f/4096.f)
                + x[((size_t)b*HW_ + e)*C_ + (256 + c)];
        g_out2[((size_t)(b*512 + 256 + c))*HW_ + e] = v;
    }
}

// ---------------- L2 norms of f rows ----------------
__global__ void norms_kernel() {
    int bc = blockIdx.x;
    int tid = threadIdx.x;
    const float* fr = g_fre + (size_t)bc*HW_;
    const float* fi = g_fim + (size_t)bc*HW_;
    float s = 0.f;
    for (int i = tid; i < HW_; i += 256) {
        float a = fr[i], b = fi[i];
        s += a*a + b*b;
    }
    for (int o = 16; o; o >>= 1) s += __shfl_xor_sync(0xffffffffu, s, o);
    __shared__ float red[8];
    if ((tid & 31) == 0) red[tid>>5] = s;
    __syncthreads();
    if (tid < 8) {
        float v = red[tid];
        for (int o = 4; o; o >>= 1) v += __shfl_xor_sync(0xffu, v, o);
        if (tid == 0) g_invn[bc] = 1.f / fmaxf(sqrtf(v), 1e-12f);
    }
}

// ---------------- attn partial GEMM ----------------
__global__ void attn_gemm_kernel() {
    int bh = blockIdx.x >> 2, nq = blockIdx.x & 3;
    int tid = threadIdx.x;
    __shared__ float sre[32*65], sim[32*65];
    const float* fr = g_fre + (size_t)bh*CPH_*HW_ + nq*1024;
    const float* fi = g_fim + (size_t)bh*CPH_*HW_ + nq*1024;
    int p0 = tid*4;
    int c = p0 >> 5, d0 = p0 & 31;
    float ar[4] = {0,0,0,0}, ai[4] = {0,0,0,0};
    for (int n0 = 0; n0 < 1024; n0 += 64) {
        __syncthreads();
        for (int e = tid; e < 2048; e += 256) {
            int cc = e >> 6, nn = e & 63;
            sre[cc*65+nn] = fr[(size_t)cc*HW_ + n0 + nn];
            sim[cc*65+nn] = fi[(size_t)cc*HW_ + n0 + nn];
        }
        __syncthreads();
        for (int nn = 0; nn < 64; nn++) {
            float cr = sre[c*65+nn], ci = sim[c*65+nn];
#pragma unroll
            for (int q = 0; q < 4; q++) {
                float dr = sre[(d0+q)*65+nn], di = sim[(d0+q)*65+nn];
                ar[q] += cr*dr - ci*di;
                ai[q] += cr*di + ci*dr;
            }
        }
    }
    float* dst = g_attnS + ((size_t)(nq*64 + bh)*1024 + p0)*2;
#pragma unroll
    for (int q = 0; q < 4; q++) { dst[q*2] = ar[q]; dst[q*2+1] = ai[q]; }
}

// ---------------- attn finalize ----------------
__global__ void attn_fin_kernel(const float* __restrict__ temp) {
    int bh = blockIdx.x;
    int head = bh & 7;
    int tid = threadIdx.x;
    __shared__ float ar_[32*33], ai_[32*33];
    float tmp = temp[head];
    for (int p = tid; p < 1024; p += 256) {
        int cc = p >> 5, dd = p & 31;
        float sr = 0.f, si = 0.f;
#pragma unroll
        for (int q = 0; q < 4; q++) {
            const float* src = g_attnS + ((size_t)(q*64 + bh)*1024 + p)*2;
            sr += src[0]; si += src[1];
        }
        float sc = g_invn[bh*32 + cc] * g_invn[bh*32 + dd] * tmp;
        ar_[cc*33+dd] = sr*sc;
        ai_[cc*33+dd] = si*sc;
    }
    __syncthreads();
    int w = tid >> 5, lane = tid & 31;
    for (int r = w; r < 32; r += 8) {
        float vr = ar_[r*33+lane];
        float m = vr;
        for (int o = 16; o; o >>= 1) m = fmaxf(m, __shfl_xor_sync(0xffffffffu, m, o));
        float e = expf(vr - m); float s = e;
        for (int o = 16; o; o >>= 1) s += __shfl_xor_sync(0xffffffffu, s, o);
        ar_[r*33+lane] = e / s;
        float vi = ai_[r*33+lane];
        m = vi;
        for (int o = 16; o; o >>= 1) m = fmaxf(m, __shfl_xor_sync(0xffffffffu, m, o));
        e = expf(vi - m); s = e;
        for (int o = 16; o; o >>= 1) s += __shfl_xor_sync(0xffffffffu, s, o);
        ai_[r*33+lane] = e / s;
    }
    __syncthreads();
    for (int p = tid; p < 1024; p += 256) {
        int k = p >> 5, dd = p & 31;
        float accr = 0.f, acci = 0.f;
#pragma unroll
        for (int cc = 0; cc < 32; cc++) {
            float2 w2 = g_twid[((k*cc) & 31) * 128];
            float wr = w2.x, wi = -w2.y;
            float xr = ar_[cc*33+dd], xi = ai_[cc*33+dd];
            accr += wr*xr - wi*xi;
            acci += wr*xi + wi*xr;
        }
        g_attn2[(size_t)bh*1024 + p] = make_float2(accr*(1.f/32.f), acci*(1.f/32.f));
    }
}

// ---------------- out row ----------------
#define SKW(i) ((i) + ((i) >> 7))
__global__ void outrow_kernel(const float* __restrict__ x) {
    __shared__ float sr[4128], si[4128];
    __shared__ float2 a2[32];
    int gid = blockIdx.x;
    int bh = gid >> 5, k = gid & 31;
    int b = gid >> 8, cg = gid & 255;
    int tid = threadIdx.x;
    if (tid < 32) a2[tid] = g_attn2[(size_t)bh*1024 + k*32 + tid];
    __syncthreads();
    const float* fr = g_fre + (size_t)bh*CPH_*HW_;
    const float* fi = g_fim + (size_t)bh*CPH_*HW_;
    for (int nn = tid; nn < 4096; nn += 256) {
        float accr = 0.f, acci = 0.f;
#pragma unroll
        for (int d = 0; d < 32; d++) {
            float frv = fr[(size_t)d*HW_ + nn], fiv = fi[(size_t)d*HW_ + nn];
            float2 a = a2[d];
            accr += a.x*frv - a.y*fiv;
            acci += a.x*fiv + a.y*frv;
        }
        int rb = __brev(nn) >> 20;
        sr[SKW(rb)] = accr;
        si[SKW(rb)] = acci;
    }
    for (int s = 1; s <= 12; s++) {
        int hm = 1 << (s-1);
        int tw = 4096 >> s;
        __syncthreads();
        for (int t = tid; t < 2048; t += 256) {
            int pos = t & (hm-1);
            int base = ((t >> (s-1)) << s) | pos;
            float2 w = g_twid[pos*tw];
            float wr = w.x, wi = -w.y;
            int i1 = SKW(base), i2 = SKW(base+hm);
            float br = sr[i2], bi = si[i2];
            float tr = br*wr - bi*wi, ti = br*wi + bi*wr;
            float a0 = sr[i1], a1 = si[i1];
            sr[i1] = a0 + tr; si[i1] = a1 + ti;
            sr[i2] = a0 - tr; si[i2] = a1 - ti;
        }
    }
    __syncthreads();
    for (int nn = tid; nn < 4096; nn += 256) {
        float re = sr[SKW(nn)], im = si[SKW(nn)];
        float v = sqrtf(re*re + im*im) * (1.f/4096.f)
                + x[((size_t)b*HW_ + nn)*C_ + cg];
        g_out2[((size_t)(b*512) + cg)*HW_ + nn] = v;
    }
}

// ---------------- gating MLP ----------------
__global__ void g1_kernel(const float* __restrict__ w1w, const float* __restrict__ w1b,
                          const float* __restrict__ bg, const float* __restrict__ bb,
                          const float* __restrict__ bm, const float* __restrict__ bv) {
    __shared__ float sw[HID_*DD_];
    __shared__ float sa[HID_], st[HID_];
    int b = blockIdx.y;
    int tid = threadIdx.x;
    int n = blockIdx.x*256 + tid;
    for (int e = tid; e < HID_*DD_; e += 256) sw[e] = w1w[e];
    if (tid < HID_) {
        float s = bg[tid] * rsqrtf(bv[tid] + 1e-5f);
        sa[tid] = s;
        st[tid] = w1b[tid]*s + bb[tid] - bm[tid]*s;
    }
    __syncthreads();
    float acc[HID_];
#pragma unroll
    for (int o = 0; o < HID_; o++) acc[o] = 0.f;
    const float* fr = g_fre + (size_t)b*DD_*HW_ + n;
    for (int c = 0; c < DD_; c++) {
        float v = fr[(size_t)c*HW_];
#pragma unroll
        for (int o = 0; o < HID_; o++) acc[o] += v * sw[o*DD_ + c];
    }
#pragma unroll
    for (int o = 0; o < HID_; o++)
        g_g1[((size_t)(b*HID_ + o))*HW_ + n] = fmaxf(acc[o]*sa[o] + st[o], 0.f);
}

__global__ void gate_kernel(const float* __restrict__ w2w, const float* __restrict__ w2b) {
    __shared__ float sw[DD_*HID_];
    __shared__ float sb[DD_];
    int b = blockIdx.y;
    int tid = threadIdx.x;
    int n = blockIdx.x*256 + tid;
    for (int e = tid; e < DD_*HID_; e += 256) sw[e] = w2w[e];
    if (tid < DD_) sb[tid] = w2b[tid];
    __syncthreads();
    float gv[HID_];
#pragma unroll
    for (int o = 0; o < HID_; o++) gv[o] = g_g1[((size_t)(b*HID_ + o))*HW_ + n];
    for (int co = 0; co < DD_; co++) {
        float a = sb[co];
#pragma unroll
        for (int o = 0; o < HID_; o++) a += sw[co*HID_ + o] * gv[o];
        float gt = 1.f / (1.f + expf(-a));
        size_t idx = ((size_t)(b*DD_ + co))*HW_ + n;
        g_gfre[idx] = gt * g_fre[idx];
        g_gfim[idx] = gt * g_fim[idx];
    }
}

// ---------------- final projection via tf32 mma: M=n(128), N=o(128), K=512 -------
// grid (4 o-tiles, 32 n-tiles, 8 b), 256 threads = 8 warps (4 m x 2 n)
__global__ void proj_mma_kernel(const float* __restrict__ pw, const float* __restrict__ pb,
                                float* __restrict__ out) {
    __shared__ uint32_t xs[128][20];   // [n][k]
    __shared__ uint32_t ws[128][20];   // [o][k]
    int b = blockIdx.z, nt = blockIdx.y, ot = blockIdx.x;
    int tid = threadIdx.x, lane = tid & 31, warp = tid >> 5;
    int wm = warp & 3, wn = warp >> 2;
    int g = lane >> 2, t = lane & 3;
    float acc[2][8][4];
#pragma unroll
    for (int i = 0; i < 2; i++)
#pragma unroll
        for (int j = 0; j < 8; j++)
#pragma unroll
            for (int q = 0; q < 4; q++) acc[i][j][q] = 0.f;

    int n0g = nt*128, o0g = ot*128;
    for (int kc = 0; kc < 512; kc += 16) {
        __syncthreads();
#pragma unroll
        for (int r = 0; r < 2; r++) {
            int e = tid + r*256;
            int k = e >> 5, n4 = e & 31;
            float4 v = *(const float4*)&g_out2[((size_t)(b*512 + kc + k))*HW_ + n0g + n4*4];
            xs[n4*4+0][k] = f2tf(v.x);
            xs[n4*4+1][k] = f2tf(v.y);
            xs[n4*4+2][k] = f2tf(v.z);
            xs[n4*4+3][k] = f2tf(v.w);
        }
#pragma unroll
        for (int r = 0; r < 2; r++) {
            int e = tid + r*256;
            int o = e >> 2, ch = e & 3;
            float4 v = *(const float4*)&pw[(size_t)(o0g + o)*512 + kc + ch*4];
            uint4 u = make_uint4(f2tf(v.x), f2tf(v.y), f2tf(v.z), f2tf(v.w));
            *(uint4*)&ws[o][ch*4] = u;
        }
        __syncthreads();
#pragma unroll
        for (int ks = 0; ks < 16; ks += 8) {
            int kr = ks + t;
            uint32_t a[2][4];
#pragma unroll
            for (int mi = 0; mi < 2; mi++) {
                int m0 = wm*32 + mi*16 + g;
                a[mi][0] = xs[m0][kr];
                a[mi][1] = xs[m0+8][kr];
                a[mi][2] = xs[m0][kr+4];
                a[mi][3] = xs[m0+8][kr+4];
            }
#pragma unroll
            for (int ni = 0; ni < 8; ni++) {
                int n0 = wn*64 + ni*8 + g;
                uint32_t b0 = ws[n0][kr];
                uint32_t b1 = ws[n0][kr+4];
                mma8(acc[0][ni], a[0], b0, b1);
                mma8(acc[1][ni], a[1], b0, b1);
            }
        }
    }
    // epilogue: rows = n, cols = o; add bias, direct v2 stores
#pragma unroll
    for (int mi = 0; mi < 2; mi++) {
#pragma unroll
        for (int half = 0; half < 2; half++) {
            int n = n0g + wm*32 + mi*16 + g + half*8;
#pragma unroll
            for (int ni = 0; ni < 8; ni++) {
                int o = o0g + wn*64 + ni*8 + 2*t;
                float2 bias = *(const float2*)&pb[o];
                float v0 = acc[mi][ni][half*2+0] + bias.x;
                float v1 = acc[mi][ni][half*2+1] + bias.y;
                *(float2*)&out[((size_t)b*HW_ + n)*C_ + o] = make_float2(v0, v1);
            }
        }
    }
}

// ---------------- launch ----------------
extern "C" void kernel_launch(void* const* d_in, const int* in_sizes, int n_in,
                              void* d_out, int out_size) {
    const float* x       = (const float*)d_in[0];
    const float* conv2_w = (const float*)d_in[1];
    const float* conv2_b = (const float*)d_in[2];
    const float* bn2_g   = (const float*)d_in[3];
    const float* bn2_b   = (const float*)d_in[4];
    const float* bn2_m   = (const float*)d_in[5];
    const float* bn2_v   = (const float*)d_in[6];
    const float* temp    = (const float*)d_in[7];
    const float* w1_w    = (const float*)d_in[8];
    const float* w1_b    = (const float*)d_in[9];
    const float* bnw_g   = (const float*)d_in[10];
    const float* bnw_b   = (const float*)d_in[11];
    const float* bnw_m   = (const float*)d_in[12];
    const float* bnw_v   = (const float*)d_in[13];
    const float* w2_w    = (const float*)d_in[14];
    const float* w2_b    = (const float*)d_in[15];
    const float* proj_w  = (const float*)d_in[16];
    const float* proj_b  = (const float*)d_in[17];
    float* out = (float*)d_out;

    prep_kernel<<<1024, 256>>>(conv2_w);
    conv_mma_kernel<<<dim3(2, 32, 8), 256>>>(x, conv2_b, bn2_g, bn2_b, bn2_m, bn2_v);
    fft2_fwd_kernel<<<2048, 256>>>();
    norms_kernel<<<2048, 256>>>();
    attn_gemm_kernel<<<256, 256>>>();
    attn_fin_kernel<<<64, 256>>>(temp);
    outrow_kernel<<<2048, 256>>>(x);
    g1_kernel<<<dim3(16, 8), 256>>>(w1_w, w1_b, bnw_g, bnw_b, bnw_m, bnw_v);
    gate_kernel<<<dim3(16, 8), 256>>>(w2_w, w2_b);
    ifft2_kernel<<<2048, 256>>>(x);
    proj_mma_kernel<<<dim3(4, 32, 8), 256>>>(proj_w, proj_b, out);
}

// round 4
// speedup vs baseline: 2.1731x; 1.2012x over previous
#include <cuda_runtime.h>
#include <math.h>
#include <stdint.h>

#define B_  8
#define C_  512
#define DD_ 256
#define HW_ 4096
#define HEADS_ 8
#define CPH_ 32
#define HID_ 16

// ---------------- scratch (static device globals; no allocation) ----------------
__device__ float  g_wt[9*256*512];          // conv weights [tap][co][cin]
__device__ float2 g_twid[4096];             // e^{-2*pi*i*k/4096}, FULL circle
__device__ float  g_y   [(size_t)B_*DD_*HW_];   // conv+bn+relu output
__device__ float  g_fre [(size_t)B_*DD_*HW_];   // fft2 real
__device__ float  g_fim [(size_t)B_*DD_*HW_];   // fft2 imag
__device__ float  g_g1  [(size_t)B_*HID_*HW_];
__device__ float  g_attnS[64*64*64];        // [bh][64][64] G G^T
__device__ float2 g_attn2[64*1024];         // softmaxed + ifft32-folded attn
__device__ float  g_or  [(size_t)B_*DD_*HW_];   // attn_apply out re
__device__ float  g_oi  [(size_t)B_*DD_*HW_];   // attn_apply out im
__device__ float  g_out2[(size_t)B_*C_*HW_];    // concat(out_f2,out_l2)+x2d

// ---------------- tf32 helpers ----------------
__device__ __forceinline__ uint32_t f2tf(float f) {
    uint32_t u;
    asm("cvt.rna.tf32.f32 %0, %1;" : "=r"(u) : "f"(f));
    return u;
}
__device__ __forceinline__ void mma8(float c[4], const uint32_t a[4], uint32_t b0, uint32_t b1) {
    asm volatile("mma.sync.aligned.m16n8k8.row.col.f32.tf32.tf32.f32 "
        "{%0,%1,%2,%3}, {%4,%5,%6,%7}, {%8,%9}, {%0,%1,%2,%3};"
        : "+f"(c[0]), "+f"(c[1]), "+f"(c[2]), "+f"(c[3])
        : "r"(a[0]), "r"(a[1]), "r"(a[2]), "r"(a[3]), "r"(b0), "r"(b1));
}

// ---------------- prep: twiddles + conv weight transpose ----------------
__global__ void prep_kernel(const float* __restrict__ cw) {
    int tid = blockIdx.x*blockDim.x + threadIdx.x;
    int stride = gridDim.x*blockDim.x;
    if (tid < 4096) {
        float s, c;
        sincosf(-6.28318530717958647692f * (float)tid / 4096.f, &s, &c);
        g_twid[tid] = make_float2(c, s);
    }
    for (int e = tid; e < 9*256*512; e += stride) {
        int tap = e / (256*512);
        int rem = e - tap*256*512;
        int co = rem >> 9;
        int cin = rem & 511;
        g_wt[e] = cw[(co*512 + cin)*9 + tap];
    }
}

// ---------------- conv via tf32 mma: 128co x 128pos tiles ----------------
__global__ void conv_mma_kernel(const float* __restrict__ x, const float* __restrict__ cb,
                                const float* __restrict__ bg, const float* __restrict__ bb,
                                const float* __restrict__ bm, const float* __restrict__ bv) {
    __shared__ uint32_t xs[128][20];   // [pos][k], pad 20
    __shared__ uint32_t ws[128][20];   // [co ][k]
    int b = blockIdx.z, pt = blockIdx.y, ct = blockIdx.x;
    int tid = threadIdx.x, lane = tid & 31, warp = tid >> 5;
    int wm = warp & 3, wn = warp >> 2;
    int g = lane >> 2, t = lane & 3;
    float acc[2][8][4];
#pragma unroll
    for (int i = 0; i < 2; i++)
#pragma unroll
        for (int j = 0; j < 8; j++)
#pragma unroll
            for (int q = 0; q < 4; q++) acc[i][j][q] = 0.f;

    int pos0 = pt*128;
    for (int tap = 0; tap < 9; tap++) {
        int dh = 3*((tap/3) - 1), dw = 3*((tap%3) - 1);
        const float* wtp = g_wt + ((size_t)tap*256 + ct*128)*512;
        for (int kc = 0; kc < 512; kc += 16) {
            __syncthreads();
#pragma unroll
            for (int r = 0; r < 2; r++) {
                int e = tid + r*256;
                int pos = e >> 2, ch = e & 3;
                int gp = pos0 + pos;
                int ih = (gp >> 6) + dh, iw = (gp & 63) + dw;
                float4 v = make_float4(0.f, 0.f, 0.f, 0.f);
                if ((unsigned)ih < 64u && (unsigned)iw < 64u)
                    v = *(const float4*)&x[((size_t)(b*HW_) + ih*64 + iw)*C_ + kc + ch*4];
                uint4 u = make_uint4(f2tf(v.x), f2tf(v.y), f2tf(v.z), f2tf(v.w));
                *(uint4*)&xs[pos][ch*4] = u;
            }
#pragma unroll
            for (int r = 0; r < 2; r++) {
                int e = tid + r*256;
                int co = e >> 2, ch = e & 3;
                float4 v = *(const float4*)&wtp[(size_t)co*512 + kc + ch*4];
                uint4 u = make_uint4(f2tf(v.x), f2tf(v.y), f2tf(v.z), f2tf(v.w));
                *(uint4*)&ws[co][ch*4] = u;
            }
            __syncthreads();
#pragma unroll
            for (int ks = 0; ks < 16; ks += 8) {
                int kr = ks + t;
                uint32_t a[2][4];
#pragma unroll
                for (int mi = 0; mi < 2; mi++) {
                    int m0 = wm*32 + mi*16 + g;
                    a[mi][0] = ws[m0][kr];
                    a[mi][1] = ws[m0+8][kr];
                    a[mi][2] = ws[m0][kr+4];
                    a[mi][3] = ws[m0+8][kr+4];
                }
#pragma unroll
                for (int ni = 0; ni < 8; ni++) {
                    int n0 = wn*64 + ni*8 + g;
                    uint32_t b0 = xs[n0][kr];
                    uint32_t b1 = xs[n0][kr+4];
                    mma8(acc[0][ni], a[0], b0, b1);
                    mma8(acc[1][ni], a[1], b0, b1);
                }
            }
        }
    }
#pragma unroll
    for (int mi = 0; mi < 2; mi++) {
#pragma unroll
        for (int half = 0; half < 2; half++) {
            int o = ct*128 + wm*32 + mi*16 + g + half*8;
            float s = bg[o] * rsqrtf(bv[o] + 1e-5f);
            float t0 = cb[o]*s + bb[o] - bm[o]*s;
            float* dst = g_y + ((size_t)(b*DD_ + o))*HW_;
#pragma unroll
            for (int ni = 0; ni < 8; ni++) {
                int pos = pos0 + wn*64 + ni*8 + 2*t;
                float v0 = fmaxf(acc[mi][ni][half*2+0]*s + t0, 0.f);
                float v1 = fmaxf(acc[mi][ni][half*2+1]*s + t0, 0.f);
                *(float2*)&dst[pos] = make_float2(v0, v1);
            }
        }
    }
}

// ---------------- 64x64 2D FFT core (shared memory, radix-2) ----------------
__device__ __forceinline__ void fft64_2d(float* sr, float* si, int tid, float sign) {
    for (int s = 1; s <= 6; s++) {
        int hm = 1 << (s-1);
        int tw = 4096 >> s;
        __syncthreads();
        for (int t = tid; t < 2048; t += 256) {
            int j = t >> 6, r = t & 63;
            int pos = j & (hm-1);
            int base = r*65 + (((j >> (s-1)) << s) | pos);
            float2 w = g_twid[pos*tw];
            float wr = w.x, wi = sign*w.y;
            int i2 = base + hm;
            float br = sr[i2], bi = si[i2];
            float tr = br*wr - bi*wi, ti = br*wi + bi*wr;
            float ar = sr[base], ai = si[base];
            sr[base] = ar + tr; si[base] = ai + ti;
            sr[i2]   = ar - tr; si[i2]   = ai - ti;
        }
    }
    __syncthreads();
    for (int e = tid; e < 4096; e += 256) {
        int r = e >> 6, cc = e & 63;
        int br = __brev(r) >> 26;
        if (r < br) {
            float a = sr[r*65+cc]; sr[r*65+cc] = sr[br*65+cc]; sr[br*65+cc] = a;
            float b = si[r*65+cc]; si[r*65+cc] = si[br*65+cc]; si[br*65+cc] = b;
        }
    }
    for (int s = 1; s <= 6; s++) {
        int hm = 1 << (s-1);
        int tw = 4096 >> s;
        __syncthreads();
        for (int t = tid; t < 2048; t += 256) {
            int j = t >> 6, cc = t & 63;
            int pos = j & (hm-1);
            int rowb = ((j >> (s-1)) << s) | pos;
            int base = rowb*65 + cc;
            int i2 = base + hm*65;
            float2 w = g_twid[pos*tw];
            float wr = w.x, wi = sign*w.y;
            float br = sr[i2], bi = si[i2];
            float tr = br*wr - bi*wi, ti = br*wi + bi*wr;
            float ar = sr[base], ai = si[base];
            sr[base] = ar + tr; si[base] = ai + ti;
            sr[i2]   = ar - tr; si[i2]   = ai - ti;
        }
    }
    __syncthreads();
}

__global__ void fft2_fwd_kernel() {
    __shared__ float sr[64*65], si[64*65];
    int bc = blockIdx.x;
    int tid = threadIdx.x;
    const float* src = g_y + (size_t)bc*HW_;
    for (int e = tid; e < 4096; e += 256) {
        int r = e >> 6, w = e & 63;
        int bw = __brev(w) >> 26;
        sr[r*65 + bw] = src[e];
        si[r*65 + bw] = 0.f;
    }
    fft64_2d(sr, si, tid, 1.f);
    float* dr = g_fre + (size_t)bc*HW_;
    float* di = g_fim + (size_t)bc*HW_;
    for (int e = tid; e < 4096; e += 256) {
        dr[e] = sr[(e>>6)*65 + (e&63)];
        di[e] = si[(e>>6)*65 + (e&63)];
    }
}

// ---------------- attention scores: S = G G^T (G = [Fr; Fi], 64 x 4096) ----------
// one block per bh; 8 warps = 4 m-tiles(16) x 2 n-halves(32)
__global__ void attn_gemm64_kernel() {
    __shared__ uint32_t gs[64][36];
    int bh = blockIdx.x;
    int tid = threadIdx.x, lane = tid & 31, warp = tid >> 5;
    int wm = warp & 3, wn = warp >> 2;
    int g = lane >> 2, t = lane & 3;
    float acc[4][4];
#pragma unroll
    for (int i = 0; i < 4; i++)
#pragma unroll
        for (int q = 0; q < 4; q++) acc[i][q] = 0.f;
    const float* fr = g_fre + (size_t)bh*CPH_*HW_;
    const float* fi = g_fim + (size_t)bh*CPH_*HW_;
    for (int k0 = 0; k0 < HW_; k0 += 32) {
        __syncthreads();
#pragma unroll
        for (int r = 0; r < 2; r++) {
            int e = tid + r*256;
            int row = e >> 3, kq = e & 7;
            const float* src = (row < 32) ? (fr + (size_t)row*HW_) : (fi + (size_t)(row-32)*HW_);
            float4 v = *(const float4*)&src[k0 + kq*4];
            uint4 u = make_uint4(f2tf(v.x), f2tf(v.y), f2tf(v.z), f2tf(v.w));
            *(uint4*)&gs[row][kq*4] = u;
        }
        __syncthreads();
#pragma unroll
        for (int ks = 0; ks < 32; ks += 8) {
            int kr = ks + t;
            uint32_t a[4];
            a[0] = gs[wm*16+g][kr];
            a[1] = gs[wm*16+g+8][kr];
            a[2] = gs[wm*16+g][kr+4];
            a[3] = gs[wm*16+g+8][kr+4];
#pragma unroll
            for (int ni = 0; ni < 4; ni++) {
                int n0 = wn*32 + ni*8 + g;
                mma8(acc[ni], a, gs[n0][kr], gs[n0][kr+4]);
            }
        }
    }
    float* S = g_attnS + (size_t)bh*64*64;
#pragma unroll
    for (int ni = 0; ni < 4; ni++) {
        int d = wn*32 + ni*8 + 2*t;
        int c0 = wm*16 + g;
        *(float2*)&S[(size_t)c0*64 + d]     = make_float2(acc[ni][0], acc[ni][1]);
        *(float2*)&S[(size_t)(c0+8)*64 + d] = make_float2(acc[ni][2], acc[ni][3]);
    }
}

// ---------------- attn finalize: scale (norms from diag), softmax, ifft32 fold ----
__global__ void attn_fin_kernel(const float* __restrict__ temp) {
    int bh = blockIdx.x;
    int head = bh & 7;
    int tid = threadIdx.x;
    __shared__ float ar_[32*33], ai_[32*33];
    __shared__ float inv[32];
    const float* S = g_attnS + (size_t)bh*64*64;
    if (tid < 32)
        inv[tid] = rsqrtf(fmaxf(S[tid*64 + tid] + S[(32+tid)*64 + 32+tid], 1e-24f));
    __syncthreads();
    float tmp = temp[head];
    for (int p = tid; p < 1024; p += 256) {
        int cc = p >> 5, dd = p & 31;
        float sre = S[cc*64 + dd] - S[(32+cc)*64 + (32+dd)];
        float sim = S[cc*64 + (32+dd)] + S[(32+cc)*64 + dd];
        float sc = inv[cc] * inv[dd] * tmp;
        ar_[cc*33+dd] = sre*sc;
        ai_[cc*33+dd] = sim*sc;
    }
    __syncthreads();
    int w = tid >> 5, lane = tid & 31;
    for (int r = w; r < 32; r += 8) {
        float vr = ar_[r*33+lane];
        float m = vr;
        for (int o = 16; o; o >>= 1) m = fmaxf(m, __shfl_xor_sync(0xffffffffu, m, o));
        float e = expf(vr - m); float s = e;
        for (int o = 16; o; o >>= 1) s += __shfl_xor_sync(0xffffffffu, s, o);
        ar_[r*33+lane] = e / s;
        float vi = ai_[r*33+lane];
        m = vi;
        for (int o = 16; o; o >>= 1) m = fmaxf(m, __shfl_xor_sync(0xffffffffu, m, o));
        e = expf(vi - m); s = e;
        for (int o = 16; o; o >>= 1) s += __shfl_xor_sync(0xffffffffu, s, o);
        ai_[r*33+lane] = e / s;
    }
    __syncthreads();
    for (int p = tid; p < 1024; p += 256) {
        int k = p >> 5, dd = p & 31;
        float accr = 0.f, acci = 0.f;
#pragma unroll
        for (int cc = 0; cc < 32; cc++) {
            float2 w2 = g_twid[((k*cc) & 31) * 128];
            float wr = w2.x, wi = -w2.y;
            float xr = ar_[cc*33+dd], xi = ai_[cc*33+dd];
            accr += wr*xr - wi*xi;
            acci += wr*xi + wi*xr;
        }
        g_attn2[(size_t)bh*1024 + p] = make_float2(accr*(1.f/32.f), acci*(1.f/32.f));
    }
}

// ---------------- attn apply: out[k][n] = sum_d attn2[k][d] * f[d][n] -------------
// grid (32 nchunks, 64 bh); f chunk staged once, reused by all 32 k
__global__ void attn_apply_kernel() {
    __shared__ float sfr[32][132], sfi[32][132];
    __shared__ float2 a2s[32][32];
    int nc = blockIdx.x, bh = blockIdx.y;
    int tid = threadIdx.x;
    for (int p = tid; p < 1024; p += 256)
        a2s[p>>5][p&31] = g_attn2[(size_t)bh*1024 + p];
    const float* fr = g_fre + (size_t)bh*CPH_*HW_ + nc*128;
    const float* fi = g_fim + (size_t)bh*CPH_*HW_ + nc*128;
    for (int e = tid; e < 1024; e += 256) {
        int d = e >> 5, j = e & 31;
        *(float4*)&sfr[d][j*4] = *(const float4*)&fr[(size_t)d*HW_ + j*4];
        *(float4*)&sfi[d][j*4] = *(const float4*)&fi[(size_t)d*HW_ + j*4];
    }
    __syncthreads();
    int tx = tid & 15, ty = tid >> 4;
    int k0 = ty*2, n0 = tx*8;
    float ar0[8], ai0[8], ar1[8], ai1[8];
#pragma unroll
    for (int j = 0; j < 8; j++) { ar0[j]=0.f; ai0[j]=0.f; ar1[j]=0.f; ai1[j]=0.f; }
#pragma unroll
    for (int d = 0; d < 32; d++) {
        float2 a0 = a2s[k0][d], a1 = a2s[k0+1][d];
        float4 f0 = *(float4*)&sfr[d][n0], f1 = *(float4*)&sfr[d][n0+4];
        float4 h0 = *(float4*)&sfi[d][n0], h1 = *(float4*)&sfi[d][n0+4];
        float frv[8] = {f0.x,f0.y,f0.z,f0.w,f1.x,f1.y,f1.z,f1.w};
        float fiv[8] = {h0.x,h0.y,h0.z,h0.w,h1.x,h1.y,h1.z,h1.w};
#pragma unroll
        for (int j = 0; j < 8; j++) {
            ar0[j] += a0.x*frv[j] - a0.y*fiv[j];
            ai0[j] += a0.x*fiv[j] + a0.y*frv[j];
            ar1[j] += a1.x*frv[j] - a1.y*fiv[j];
            ai1[j] += a1.x*fiv[j] + a1.y*frv[j];
        }
    }
    size_t base0 = ((size_t)(bh*32 + k0))*HW_ + nc*128 + n0;
    size_t base1 = base0 + HW_;
    *(float4*)&g_or[base0]   = make_float4(ar0[0],ar0[1],ar0[2],ar0[3]);
    *(float4*)&g_or[base0+4] = make_float4(ar0[4],ar0[5],ar0[6],ar0[7]);
    *(float4*)&g_oi[base0]   = make_float4(ai0[0],ai0[1],ai0[2],ai0[3]);
    *(float4*)&g_oi[base0+4] = make_float4(ai0[4],ai0[5],ai0[6],ai0[7]);
    *(float4*)&g_or[base1]   = make_float4(ar1[0],ar1[1],ar1[2],ar1[3]);
    *(float4*)&g_or[base1+4] = make_float4(ar1[4],ar1[5],ar1[6],ar1[7]);
    *(float4*)&g_oi[base1]   = make_float4(ai1[0],ai1[1],ai1[2],ai1[3]);
    *(float4*)&g_oi[base1+4] = make_float4(ai1[4],ai1[5],ai1[6],ai1[7]);
}

// ---------------- row ifft4096 + abs + residual, lower half of out2 ---------------
#define SKW(i) ((i) + ((i) >> 7))
__global__ void ifft_row_kernel(const float* __restrict__ x) {
    __shared__ float sr[4128], si[4128];
    int gid = blockIdx.x;              // b*256 + cg
    int b = gid >> 8, cg = gid & 255;
    int tid = threadIdx.x;
    const float* pr = g_or + (size_t)gid*HW_;
    const float* pi = g_oi + (size_t)gid*HW_;
    for (int nn = tid; nn < 4096; nn += 256) {
        int rb = __brev(nn) >> 20;
        int d = SKW(rb);
        sr[d] = pr[nn];
        si[d] = pi[nn];
    }
    for (int s = 1; s <= 12; s++) {
        int hm = 1 << (s-1);
        int tw = 4096 >> s;
        __syncthreads();
        for (int t = tid; t < 2048; t += 256) {
            int pos = t & (hm-1);
            int base = ((t >> (s-1)) << s) | pos;
            float2 w = g_twid[pos*tw];
            float wr = w.x, wi = -w.y;
            int i1 = SKW(base), i2 = SKW(base+hm);
            float br = sr[i2], bi = si[i2];
            float tr = br*wr - bi*wi, ti = br*wi + bi*wr;
            float a0 = sr[i1], a1 = si[i1];
            sr[i1] = a0 + tr; si[i1] = a1 + ti;
            sr[i2] = a0 - tr; si[i2] = a1 - ti;
        }
    }
    __syncthreads();
    for (int nn = tid; nn < 4096; nn += 256) {
        float re = sr[SKW(nn)], im = si[SKW(nn)];
        float v = sqrtf(re*re + im*im) * (1.f/4096.f)
                + x[((size_t)b*HW_ + nn)*C_ + cg];
        g_out2[((size_t)(b*512) + cg)*HW_ + nn] = v;
    }
}

// ---------------- gating MLP stage 1 ----------------
__global__ void g1_kernel(const float* __restrict__ w1w, const float* __restrict__ w1b,
                          const float* __restrict__ bg, const float* __restrict__ bb,
                          const float* __restrict__ bm, const float* __restrict__ bv) {
    __shared__ float sw[HID_*DD_];
    __shared__ float sa[HID_], st[HID_];
    int b = blockIdx.y;
    int tid = threadIdx.x;
    int n = blockIdx.x*256 + tid;
    for (int e = tid; e < HID_*DD_; e += 256) sw[e] = w1w[e];
    if (tid < HID_) {
        float s = bg[tid] * rsqrtf(bv[tid] + 1e-5f);
        sa[tid] = s;
        st[tid] = w1b[tid]*s + bb[tid] - bm[tid]*s;
    }
    __syncthreads();
    float acc[HID_];
#pragma unroll
    for (int o = 0; o < HID_; o++) acc[o] = 0.f;
    const float* fr = g_fre + (size_t)b*DD_*HW_ + n;
    for (int c = 0; c < DD_; c++) {
        float v = fr[(size_t)c*HW_];
#pragma unroll
        for (int o = 0; o < HID_; o++) acc[o] += v * sw[o*DD_ + c];
    }
#pragma unroll
    for (int o = 0; o < HID_; o++)
        g_g1[((size_t)(b*HID_ + o))*HW_ + n] = fmaxf(acc[o]*sa[o] + st[o], 0.f);
}

// ---------------- fused gate + ifft2 + abs + residual, upper half of out2 ---------
__global__ void ifft2_gate_kernel(const float* __restrict__ x,
                                  const float* __restrict__ w2w,
                                  const float* __restrict__ w2b) {
    __shared__ float sr[64*65], si[64*65];
    __shared__ float w2s[HID_];
    int bc = blockIdx.x;               // b*256 + c
    int b = bc >> 8, c = bc & 255;
    int tid = threadIdx.x;
    if (tid < HID_) w2s[tid] = w2w[c*HID_ + tid];
    __syncthreads();
    float bias = w2b[c];
    float acc[16];
#pragma unroll
    for (int j = 0; j < 16; j++) acc[j] = bias;
    const float* g1p = g_g1 + (size_t)b*HID_*HW_;
#pragma unroll
    for (int o = 0; o < HID_; o++) {
        float w = w2s[o];
        const float* row = g1p + (size_t)o*HW_;
#pragma unroll
        for (int j = 0; j < 16; j++) acc[j] += w * row[tid + j*256];
    }
    const float* fre = g_fre + (size_t)bc*HW_;
    const float* fim = g_fim + (size_t)bc*HW_;
#pragma unroll
    for (int j = 0; j < 16; j++) {
        int e = tid + j*256;
        float gt = 1.f / (1.f + expf(-acc[j]));
        int r = e >> 6, w = e & 63;
        int bw = __brev(w) >> 26;
        sr[r*65 + bw] = gt * fre[e];
        si[r*65 + bw] = gt * fim[e];
    }
    fft64_2d(sr, si, tid, -1.f);
    for (int e = tid; e < 4096; e += 256) {
        float re = sr[(e>>6)*65 + (e&63)], im = si[(e>>6)*65 + (e&63)];
        float v = sqrtf(re*re + im*im) * (1.f/4096.f)
                + x[((size_t)b*HW_ + e)*C_ + (256 + c)];
        g_out2[((size_t)(b*512 + 256 + c))*HW_ + e] = v;
    }
}

// ---------------- final projection via tf32 mma ----------------
__global__ void proj_mma_kernel(const float* __restrict__ pw, const float* __restrict__ pb,
                                float* __restrict__ out) {
    __shared__ uint32_t xs[128][20];
    __shared__ uint32_t ws[128][20];
    int b = blockIdx.z, nt = blockIdx.y, ot = blockIdx.x;
    int tid = threadIdx.x, lane = tid & 31, warp = tid >> 5;
    int wm = warp & 3, wn = warp >> 2;
    int g = lane >> 2, t = lane & 3;
    float acc[2][8][4];
#pragma unroll
    for (int i = 0; i < 2; i++)
#pragma unroll
        for (int j = 0; j < 8; j++)
#pragma unroll
            for (int q = 0; q < 4; q++) acc[i][j][q] = 0.f;

    int n0g = nt*128, o0g = ot*128;
    for (int kc = 0; kc < 512; kc += 16) {
        __syncthreads();
#pragma unroll
        for (int r = 0; r < 2; r++) {
            int e = tid + r*256;
            int k = e >> 5, n4 = e & 31;
            float4 v = *(const float4*)&g_out2[((size_t)(b*512 + kc + k))*HW_ + n0g + n4*4];
            xs[n4*4+0][k] = f2tf(v.x);
            xs[n4*4+1][k] = f2tf(v.y);
            xs[n4*4+2][k] = f2tf(v.z);
            xs[n4*4+3][k] = f2tf(v.w);
        }
#pragma unroll
        for (int r = 0; r < 2; r++) {
            int e = tid + r*256;
            int o = e >> 2, ch = e & 3;
            float4 v = *(const float4*)&pw[(size_t)(o0g + o)*512 + kc + ch*4];
            uint4 u = make_uint4(f2tf(v.x), f2tf(v.y), f2tf(v.z), f2tf(v.w));
            *(uint4*)&ws[o][ch*4] = u;
        }
        __syncthreads();
#pragma unroll
        for (int ks = 0; ks < 16; ks += 8) {
            int kr = ks + t;
            uint32_t a[2][4];
#pragma unroll
            for (int mi = 0; mi < 2; mi++) {
                int m0 = wm*32 + mi*16 + g;
                a[mi][0] = xs[m0][kr];
                a[mi][1] = xs[m0+8][kr];
                a[mi][2] = xs[m0][kr+4];
                a[mi][3] = xs[m0+8][kr+4];
            }
#pragma unroll
            for (int ni = 0; ni < 8; ni++) {
                int n0 = wn*64 + ni*8 + g;
                uint32_t b0 = ws[n0][kr];
                uint32_t b1 = ws[n0][kr+4];
                mma8(acc[0][ni], a[0], b0, b1);
                mma8(acc[1][ni], a[1], b0, b1);
            }
        }
    }
#pragma unroll
    for (int mi = 0; mi < 2; mi++) {
#pragma unroll
        for (int half = 0; half < 2; half++) {
            int n = n0g + wm*32 + mi*16 + g + half*8;
#pragma unroll
            for (int ni = 0; ni < 8; ni++) {
                int o = o0g + wn*64 + ni*8 + 2*t;
                float2 bias = *(const float2*)&pb[o];
                float v0 = acc[mi][ni][half*2+0] + bias.x;
                float v1 = acc[mi][ni][half*2+1] + bias.y;
                *(float2*)&out[((size_t)b*HW_ + n)*C_ + o] = make_float2(v0, v1);
            }
        }
    }
}

// ---------------- launch ----------------
extern "C" void kernel_launch(void* const* d_in, const int* in_sizes, int n_in,
                              void* d_out, int out_size) {
    const float* x       = (const float*)d_in[0];
    const float* conv2_w = (const float*)d_in[1];
    const float* conv2_b = (const float*)d_in[2];
    const float* bn2_g   = (const float*)d_in[3];
    const float* bn2_b   = (const float*)d_in[4];
    const float* bn2_m   = (const float*)d_in[5];
    const float* bn2_v   = (const float*)d_in[6];
    const float* temp    = (const float*)d_in[7];
    const float* w1_w    = (const float*)d_in[8];
    const float* w1_b    = (const float*)d_in[9];
    const float* bnw_g   = (const float*)d_in[10];
    const float* bnw_b   = (const float*)d_in[11];
    const float* bnw_m   = (const float*)d_in[12];
    const float* bnw_v   = (const float*)d_in[13];
    const float* w2_w    = (const float*)d_in[14];
    const float* w2_b    = (const float*)d_in[15];
    const float* proj_w  = (const float*)d_in[16];
    const float* proj_b  = (const float*)d_in[17];
    float* out = (float*)d_out;

    prep_kernel<<<1024, 256>>>(conv2_w);
    conv_mma_kernel<<<dim3(2, 32, 8), 256>>>(x, conv2_b, bn2_g, bn2_b, bn2_m, bn2_v);
    fft2_fwd_kernel<<<2048, 256>>>();
    attn_gemm64_kernel<<<64, 256>>>();
    attn_fin_kernel<<<64, 256>>>(temp);
    attn_apply_kernel<<<dim3(32, 64), 256>>>();
    ifft_row_kernel<<<2048, 256>>>(x);
    g1_kernel<<<dim3(16, 8), 256>>>(w1_w, w1_b, bnw_g, bnw_b, bnw_m, bnw_v);
    ifft2_gate_kernel<<<2048, 256>>>(x, w2_w, w2_b);
    proj_mma_kernel<<<dim3(4, 32, 8), 256>>>(proj_w, proj_b, out);
}

// round 5
// speedup vs baseline: 2.7560x; 1.2682x over previous
#include <cuda_runtime.h>
#include <math.h>
#include <stdint.h>

#define B_  8
#define C_  512
#define DD_ 256
#define HW_ 4096
#define HEADS_ 8
#define CPH_ 32
#define HID_ 16
#define KSPLIT 8

// ---------------- scratch (static device globals; no allocation) ----------------
__device__ float  g_wt[9*256*512];          // conv weights [tap][co][cin]
__device__ float2 g_twid[4096];             // e^{-2*pi*i*k/4096}, FULL circle
__device__ float  g_y   [(size_t)B_*DD_*HW_];   // conv+bn+relu output
__device__ float  g_fre [(size_t)B_*DD_*HW_];   // fft2 real
__device__ float  g_fim [(size_t)B_*DD_*HW_];   // fft2 imag
__device__ float  g_g1  [(size_t)B_*HID_*HW_];
__device__ float  g_attnS[KSPLIT*64*64*64]; // partial S [kq][bh][64][64]
__device__ float2 g_attn2[64*1024];         // softmaxed + ifft32-folded attn
__device__ float  g_or  [(size_t)B_*DD_*HW_];   // attn_apply out re
__device__ float  g_oi  [(size_t)B_*DD_*HW_];   // attn_apply out im
__device__ float  g_out2[(size_t)B_*C_*HW_];    // concat(out_f2,out_l2)+x2d

// ---------------- tf32 helpers ----------------
__device__ __forceinline__ uint32_t f2tf(float f) {
    uint32_t u;
    asm("cvt.rna.tf32.f32 %0, %1;" : "=r"(u) : "f"(f));
    return u;
}
__device__ __forceinline__ void mma8(float c[4], const uint32_t a[4], uint32_t b0, uint32_t b1) {
    asm volatile("mma.sync.aligned.m16n8k8.row.col.f32.tf32.tf32.f32 "
        "{%0,%1,%2,%3}, {%4,%5,%6,%7}, {%8,%9}, {%0,%1,%2,%3};"
        : "+f"(c[0]), "+f"(c[1]), "+f"(c[2]), "+f"(c[3])
        : "r"(a[0]), "r"(a[1]), "r"(a[2]), "r"(a[3]), "r"(b0), "r"(b1));
}

// ---------------- prep ----------------
__global__ void prep_kernel(const float* __restrict__ cw) {
    int tid = blockIdx.x*blockDim.x + threadIdx.x;
    int stride = gridDim.x*blockDim.x;
    if (tid < 4096) {
        float s, c;
        sincosf(-6.28318530717958647692f * (float)tid / 4096.f, &s, &c);
        g_twid[tid] = make_float2(c, s);
    }
    for (int e = tid; e < 9*256*512; e += stride) {
        int tap = e / (256*512);
        int rem = e - tap*256*512;
        int co = rem >> 9;
        int cin = rem & 511;
        g_wt[e] = cw[(co*512 + cin)*9 + tap];
    }
}

// ---------------- conv via tf32 mma: 128co x 128pos tiles, KC=32 ----------------
__global__ void conv_mma_kernel(const float* __restrict__ x, const float* __restrict__ cb,
                                const float* __restrict__ bg, const float* __restrict__ bb,
                                const float* __restrict__ bm, const float* __restrict__ bv) {
    __shared__ uint32_t xs[128][36];   // [pos][k], 32 + pad 4
    __shared__ uint32_t ws[128][36];   // [co ][k]
    int b = blockIdx.z, pt = blockIdx.y, ct = blockIdx.x;
    int tid = threadIdx.x, lane = tid & 31, warp = tid >> 5;
    int wm = warp & 3, wn = warp >> 2;
    int g = lane >> 2, t = lane & 3;
    float acc[2][8][4];
#pragma unroll
    for (int i = 0; i < 2; i++)
#pragma unroll
        for (int j = 0; j < 8; j++)
#pragma unroll
            for (int q = 0; q < 4; q++) acc[i][j][q] = 0.f;

    int pos0 = pt*128;
    for (int tap = 0; tap < 9; tap++) {
        int dh = 3*((tap/3) - 1), dw = 3*((tap%3) - 1);
        const float* wtp = g_wt + ((size_t)tap*256 + ct*128)*512;
        for (int kc = 0; kc < 512; kc += 32) {
            __syncthreads();
#pragma unroll
            for (int r = 0; r < 4; r++) {
                int e = tid + r*256;
                int pos = e >> 3, ch = e & 7;
                int gp = pos0 + pos;
                int ih = (gp >> 6) + dh, iw = (gp & 63) + dw;
                float4 v = make_float4(0.f, 0.f, 0.f, 0.f);
                if ((unsigned)ih < 64u && (unsigned)iw < 64u)
                    v = *(const float4*)&x[((size_t)(b*HW_) + ih*64 + iw)*C_ + kc + ch*4];
                uint4 u = make_uint4(f2tf(v.x), f2tf(v.y), f2tf(v.z), f2tf(v.w));
                *(uint4*)&xs[pos][ch*4] = u;
            }
#pragma unroll
            for (int r = 0; r < 4; r++) {
                int e = tid + r*256;
                int co = e >> 3, ch = e & 7;
                float4 v = *(const float4*)&wtp[(size_t)co*512 + kc + ch*4];
                uint4 u = make_uint4(f2tf(v.x), f2tf(v.y), f2tf(v.z), f2tf(v.w));
                *(uint4*)&ws[co][ch*4] = u;
            }
            __syncthreads();
#pragma unroll
            for (int ks = 0; ks < 32; ks += 8) {
                int kr = ks + t;
                uint32_t a[2][4];
#pragma unroll
                for (int mi = 0; mi < 2; mi++) {
                    int m0 = wm*32 + mi*16 + g;
                    a[mi][0] = ws[m0][kr];
                    a[mi][1] = ws[m0+8][kr];
                    a[mi][2] = ws[m0][kr+4];
                    a[mi][3] = ws[m0+8][kr+4];
                }
#pragma unroll
                for (int ni = 0; ni < 8; ni++) {
                    int n0 = wn*64 + ni*8 + g;
                    uint32_t b0 = xs[n0][kr];
                    uint32_t b1 = xs[n0][kr+4];
                    mma8(acc[0][ni], a[0], b0, b1);
                    mma8(acc[1][ni], a[1], b0, b1);
                }
            }
        }
    }
#pragma unroll
    for (int mi = 0; mi < 2; mi++) {
#pragma unroll
        for (int half = 0; half < 2; half++) {
            int o = ct*128 + wm*32 + mi*16 + g + half*8;
            float s = bg[o] * rsqrtf(bv[o] + 1e-5f);
            float t0 = cb[o]*s + bb[o] - bm[o]*s;
            float* dst = g_y + ((size_t)(b*DD_ + o))*HW_;
#pragma unroll
            for (int ni = 0; ni < 8; ni++) {
                int pos = pos0 + wn*64 + ni*8 + 2*t;
                float v0 = fmaxf(acc[mi][ni][half*2+0]*s + t0, 0.f);
                float v1 = fmaxf(acc[mi][ni][half*2+1]*s + t0, 0.f);
                *(float2*)&dst[pos] = make_float2(v0, v1);
            }
        }
    }
}

// ---------------- 64x64 2D FFT core (stride = nt threads) ----------------
__device__ __forceinline__ void fft64_2d(float* sr, float* si, int tid, int nt, float sign) {
    for (int s = 1; s <= 6; s++) {
        int hm = 1 << (s-1);
        int tw = 4096 >> s;
        __syncthreads();
        for (int t = tid; t < 2048; t += nt) {
            int j = t >> 6, r = t & 63;
            int pos = j & (hm-1);
            int base = r*65 + (((j >> (s-1)) << s) | pos);
            float2 w = g_twid[pos*tw];
            float wr = w.x, wi = sign*w.y;
            int i2 = base + hm;
            float br = sr[i2], bi = si[i2];
            float tr = br*wr - bi*wi, ti = br*wi + bi*wr;
            float ar = sr[base], ai = si[base];
            sr[base] = ar + tr; si[base] = ai + ti;
            sr[i2]   = ar - tr; si[i2]   = ai - ti;
        }
    }
    __syncthreads();
    for (int e = tid; e < 4096; e += nt) {
        int r = e >> 6, cc = e & 63;
        int br = __brev(r) >> 26;
        if (r < br) {
            float a = sr[r*65+cc]; sr[r*65+cc] = sr[br*65+cc]; sr[br*65+cc] = a;
            float b = si[r*65+cc]; si[r*65+cc] = si[br*65+cc]; si[br*65+cc] = b;
        }
    }
    for (int s = 1; s <= 6; s++) {
        int hm = 1 << (s-1);
        int tw = 4096 >> s;
        __syncthreads();
        for (int t = tid; t < 2048; t += nt) {
            int j = t >> 6, cc = t & 63;
            int pos = j & (hm-1);
            int rowb = ((j >> (s-1)) << s) | pos;
            int base = rowb*65 + cc;
            int i2 = base + hm*65;
            float2 w = g_twid[pos*tw];
            float wr = w.x, wi = sign*w.y;
            float br = sr[i2], bi = si[i2];
            float tr = br*wr - bi*wi, ti = br*wi + bi*wr;
            float ar = sr[base], ai = si[base];
            sr[base] = ar + tr; si[base] = ai + ti;
            sr[i2]   = ar - tr; si[i2]   = ai - ti;
        }
    }
    __syncthreads();
}

__global__ void fft2_fwd_kernel() {
    __shared__ float sr[64*65], si[64*65];
    int bc = blockIdx.x;
    int tid = threadIdx.x;
    const float* src = g_y + (size_t)bc*HW_;
    for (int e = tid; e < 4096; e += 512) {
        int r = e >> 6, w = e & 63;
        int bw = __brev(w) >> 26;
        sr[r*65 + bw] = src[e];
        si[r*65 + bw] = 0.f;
    }
    fft64_2d(sr, si, tid, 512, 1.f);
    float* dr = g_fre + (size_t)bc*HW_;
    float* di = g_fim + (size_t)bc*HW_;
    for (int e = tid; e < 4096; e += 512) {
        dr[e] = sr[(e>>6)*65 + (e&63)];
        di[e] = si[(e>>6)*65 + (e&63)];
    }
}

// ---------------- attention scores: partial S = G G^T over k-slice ----------------
// grid (64 bh, KSPLIT kq); 8 warps = 4 m-tiles(16) x 2 n-halves(32)
__global__ void attn_gemm64_kernel() {
    __shared__ uint32_t gs[64][36];
    int bh = blockIdx.x, kq = blockIdx.y;
    int tid = threadIdx.x, lane = tid & 31, warp = tid >> 5;
    int wm = warp & 3, wn = warp >> 2;
    int g = lane >> 2, t = lane & 3;
    float acc[4][4];
#pragma unroll
    for (int i = 0; i < 4; i++)
#pragma unroll
        for (int q = 0; q < 4; q++) acc[i][q] = 0.f;
    const float* fr = g_fre + (size_t)bh*CPH_*HW_;
    const float* fi = g_fim + (size_t)bh*CPH_*HW_;
    int kbeg = kq*(HW_/KSPLIT), kend = kbeg + HW_/KSPLIT;
    for (int k0 = kbeg; k0 < kend; k0 += 32) {
        __syncthreads();
#pragma unroll
        for (int r = 0; r < 2; r++) {
            int e = tid + r*256;
            int row = e >> 3, kqq = e & 7;
            const float* src = (row < 32) ? (fr + (size_t)row*HW_) : (fi + (size_t)(row-32)*HW_);
            float4 v = *(const float4*)&src[k0 + kqq*4];
            uint4 u = make_uint4(f2tf(v.x), f2tf(v.y), f2tf(v.z), f2tf(v.w));
            *(uint4*)&gs[row][kqq*4] = u;
        }
        __syncthreads();
#pragma unroll
        for (int ks = 0; ks < 32; ks += 8) {
            int kr = ks + t;
            uint32_t a[4];
            a[0] = gs[wm*16+g][kr];
            a[1] = gs[wm*16+g+8][kr];
            a[2] = gs[wm*16+g][kr+4];
            a[3] = gs[wm*16+g+8][kr+4];
#pragma unroll
            for (int ni = 0; ni < 4; ni++) {
                int n0 = wn*32 + ni*8 + g;
                mma8(acc[ni], a, gs[n0][kr], gs[n0][kr+4]);
            }
        }
    }
    float* S = g_attnS + ((size_t)(kq*64 + bh))*4096;
#pragma unroll
    for (int ni = 0; ni < 4; ni++) {
        int d = wn*32 + ni*8 + 2*t;
        int c0 = wm*16 + g;
        *(float2*)&S[(size_t)c0*64 + d]     = make_float2(acc[ni][0], acc[ni][1]);
        *(float2*)&S[(size_t)(c0+8)*64 + d] = make_float2(acc[ni][2], acc[ni][3]);
    }
}

// ---------------- attn finalize: sum partials, scale, softmax, ifft32 fold --------
__global__ void attn_fin_kernel(const float* __restrict__ temp) {
    int bh = blockIdx.x;
    int head = bh & 7;
    int tid = threadIdx.x;
    __shared__ float Ss[4096];
    __shared__ float ar_[32*33], ai_[32*33];
    __shared__ float inv[32];
    for (int p = tid; p < 4096; p += 256) {
        float s = 0.f;
#pragma unroll
        for (int q = 0; q < KSPLIT; q++)
            s += g_attnS[((size_t)(q*64 + bh))*4096 + p];
        Ss[p] = s;
    }
    __syncthreads();
    if (tid < 32)
        inv[tid] = rsqrtf(fmaxf(Ss[tid*64 + tid] + Ss[(32+tid)*64 + 32+tid], 1e-24f));
    __syncthreads();
    float tmp = temp[head];
    for (int p = tid; p < 1024; p += 256) {
        int cc = p >> 5, dd = p & 31;
        float sre = Ss[cc*64 + dd] - Ss[(32+cc)*64 + (32+dd)];
        float sim = Ss[cc*64 + (32+dd)] + Ss[(32+cc)*64 + dd];
        float sc = inv[cc] * inv[dd] * tmp;
        ar_[cc*33+dd] = sre*sc;
        ai_[cc*33+dd] = sim*sc;
    }
    __syncthreads();
    int w = tid >> 5, lane = tid & 31;
    for (int r = w; r < 32; r += 8) {
        float vr = ar_[r*33+lane];
        float m = vr;
        for (int o = 16; o; o >>= 1) m = fmaxf(m, __shfl_xor_sync(0xffffffffu, m, o));
        float e = expf(vr - m); float s = e;
        for (int o = 16; o; o >>= 1) s += __shfl_xor_sync(0xffffffffu, s, o);
        ar_[r*33+lane] = e / s;
        float vi = ai_[r*33+lane];
        m = vi;
        for (int o = 16; o; o >>= 1) m = fmaxf(m, __shfl_xor_sync(0xffffffffu, m, o));
        e = expf(vi - m); s = e;
        for (int o = 16; o; o >>= 1) s += __shfl_xor_sync(0xffffffffu, s, o);
        ai_[r*33+lane] = e / s;
    }
    __syncthreads();
    for (int p = tid; p < 1024; p += 256) {
        int k = p >> 5, dd = p & 31;
        float accr = 0.f, acci = 0.f;
#pragma unroll
        for (int cc = 0; cc < 32; cc++) {
            float2 w2 = g_twid[((k*cc) & 31) * 128];
            float wr = w2.x, wi = -w2.y;
            float xr = ar_[cc*33+dd], xi = ai_[cc*33+dd];
            accr += wr*xr - wi*xi;
            acci += wr*xi + wi*xr;
        }
        g_attn2[(size_t)bh*1024 + p] = make_float2(accr*(1.f/32.f), acci*(1.f/32.f));
    }
}

// ---------------- attn apply ----------------
__global__ void attn_apply_kernel() {
    __shared__ float sfr[32][132], sfi[32][132];
    __shared__ float2 a2s[32][32];
    int nc = blockIdx.x, bh = blockIdx.y;
    int tid = threadIdx.x;
    for (int p = tid; p < 1024; p += 256)
        a2s[p>>5][p&31] = g_attn2[(size_t)bh*1024 + p];
    const float* fr = g_fre + (size_t)bh*CPH_*HW_ + nc*128;
    const float* fi = g_fim + (size_t)bh*CPH_*HW_ + nc*128;
    for (int e = tid; e < 1024; e += 256) {
        int d = e >> 5, j = e & 31;
        *(float4*)&sfr[d][j*4] = *(const float4*)&fr[(size_t)d*HW_ + j*4];
        *(float4*)&sfi[d][j*4] = *(const float4*)&fi[(size_t)d*HW_ + j*4];
    }
    __syncthreads();
    int tx = tid & 15, ty = tid >> 4;
    int k0 = ty*2, n0 = tx*8;
    float ar0[8], ai0[8], ar1[8], ai1[8];
#pragma unroll
    for (int j = 0; j < 8; j++) { ar0[j]=0.f; ai0[j]=0.f; ar1[j]=0.f; ai1[j]=0.f; }
#pragma unroll
    for (int d = 0; d < 32; d++) {
        float2 a0 = a2s[k0][d], a1 = a2s[k0+1][d];
        float4 f0 = *(float4*)&sfr[d][n0], f1 = *(float4*)&sfr[d][n0+4];
        float4 h0 = *(float4*)&sfi[d][n0], h1 = *(float4*)&sfi[d][n0+4];
        float frv[8] = {f0.x,f0.y,f0.z,f0.w,f1.x,f1.y,f1.z,f1.w};
        float fiv[8] = {h0.x,h0.y,h0.z,h0.w,h1.x,h1.y,h1.z,h1.w};
#pragma unroll
        for (int j = 0; j < 8; j++) {
            ar0[j] += a0.x*frv[j] - a0.y*fiv[j];
            ai0[j] += a0.x*fiv[j] + a0.y*frv[j];
            ar1[j] += a1.x*frv[j] - a1.y*fiv[j];
            ai1[j] += a1.x*fiv[j] + a1.y*frv[j];
        }
    }
    size_t base0 = ((size_t)(bh*32 + k0))*HW_ + nc*128 + n0;
    size_t base1 = base0 + HW_;
    *(float4*)&g_or[base0]   = make_float4(ar0[0],ar0[1],ar0[2],ar0[3]);
    *(float4*)&g_or[base0+4] = make_float4(ar0[4],ar0[5],ar0[6],ar0[7]);
    *(float4*)&g_oi[base0]   = make_float4(ai0[0],ai0[1],ai0[2],ai0[3]);
    *(float4*)&g_oi[base0+4] = make_float4(ai0[4],ai0[5],ai0[6],ai0[7]);
    *(float4*)&g_or[base1]   = make_float4(ar1[0],ar1[1],ar1[2],ar1[3]);
    *(float4*)&g_or[base1+4] = make_float4(ar1[4],ar1[5],ar1[6],ar1[7]);
    *(float4*)&g_oi[base1]   = make_float4(ai1[0],ai1[1],ai1[2],ai1[3]);
    *(float4*)&g_oi[base1+4] = make_float4(ai1[4],ai1[5],ai1[6],ai1[7]);
}

// ---------------- row ifft4096 + abs + residual (512 threads) ---------------------
#define SKW(i) ((i) + ((i) >> 7))
__global__ void ifft_row_kernel(const float* __restrict__ x) {
    __shared__ float sr[4128], si[4128];
    int gid = blockIdx.x;
    int b = gid >> 8, cg = gid & 255;
    int tid = threadIdx.x;
    const float* pr = g_or + (size_t)gid*HW_;
    const float* pi = g_oi + (size_t)gid*HW_;
    for (int nn = tid; nn < 4096; nn += 512) {
        int rb = __brev(nn) >> 20;
        int d = SKW(rb);
        sr[d] = pr[nn];
        si[d] = pi[nn];
    }
    for (int s = 1; s <= 12; s++) {
        int hm = 1 << (s-1);
        int tw = 4096 >> s;
        __syncthreads();
        for (int t = tid; t < 2048; t += 512) {
            int pos = t & (hm-1);
            int base = ((t >> (s-1)) << s) | pos;
            float2 w = g_twid[pos*tw];
            float wr = w.x, wi = -w.y;
            int i1 = SKW(base), i2 = SKW(base+hm);
            float br = sr[i2], bi = si[i2];
            float tr = br*wr - bi*wi, ti = br*wi + bi*wr;
            float a0 = sr[i1], a1 = si[i1];
            sr[i1] = a0 + tr; si[i1] = a1 + ti;
            sr[i2] = a0 - tr; si[i2] = a1 - ti;
        }
    }
    __syncthreads();
    for (int nn = tid; nn < 4096; nn += 512) {
        float re = sr[SKW(nn)], im = si[SKW(nn)];
        float v = sqrtf(re*re + im*im) * (1.f/4096.f)
                + x[((size_t)b*HW_ + nn)*C_ + cg];
        g_out2[((size_t)(b*512) + cg)*HW_ + nn] = v;
    }
}

// ---------------- gating MLP stage 1 ----------------
__global__ void g1_kernel(const float* __restrict__ w1w, const float* __restrict__ w1b,
                          const float* __restrict__ bg, const float* __restrict__ bb,
                          const float* __restrict__ bm, const float* __restrict__ bv) {
    __shared__ float sw[HID_*DD_];
    __shared__ float sa[HID_], st[HID_];
    int b = blockIdx.y;
    int tid = threadIdx.x;
    int n = blockIdx.x*256 + tid;
    for (int e = tid; e < HID_*DD_; e += 256) sw[e] = w1w[e];
    if (tid < HID_) {
        float s = bg[tid] * rsqrtf(bv[tid] + 1e-5f);
        sa[tid] = s;
        st[tid] = w1b[tid]*s + bb[tid] - bm[tid]*s;
    }
    __syncthreads();
    float acc[HID_];
#pragma unroll
    for (int o = 0; o < HID_; o++) acc[o] = 0.f;
    const float* fr = g_fre + (size_t)b*DD_*HW_ + n;
    for (int c = 0; c < DD_; c++) {
        float v = fr[(size_t)c*HW_];
#pragma unroll
        for (int o = 0; o < HID_; o++) acc[o] += v * sw[o*DD_ + c];
    }
#pragma unroll
    for (int o = 0; o < HID_; o++)
        g_g1[((size_t)(b*HID_ + o))*HW_ + n] = fmaxf(acc[o]*sa[o] + st[o], 0.f);
}

// ---------------- fused gate + ifft2 + abs + residual (512 threads) ---------------
__global__ void ifft2_gate_kernel(const float* __restrict__ x,
                                  const float* __restrict__ w2w,
                                  const float* __restrict__ w2b) {
    __shared__ float sr[64*65], si[64*65];
    __shared__ float w2s[HID_];
    int bc = blockIdx.x;
    int b = bc >> 8, c = bc & 255;
    int tid = threadIdx.x;
    if (tid < HID_) w2s[tid] = w2w[c*HID_ + tid];
    __syncthreads();
    float bias = w2b[c];
    float acc[8];
#pragma unroll
    for (int j = 0; j < 8; j++) acc[j] = bias;
    const float* g1p = g_g1 + (size_t)b*HID_*HW_;
#pragma unroll
    for (int o = 0; o < HID_; o++) {
        float w = w2s[o];
        const float* row = g1p + (size_t)o*HW_;
#pragma unroll
        for (int j = 0; j < 8; j++) acc[j] += w * row[tid + j*512];
    }
    const float* fre = g_fre + (size_t)bc*HW_;
    const float* fim = g_fim + (size_t)bc*HW_;
#pragma unroll
    for (int j = 0; j < 8; j++) {
        int e = tid + j*512;
        float gt = 1.f / (1.f + expf(-acc[j]));
        int r = e >> 6, w = e & 63;
        int bw = __brev(w) >> 26;
        sr[r*65 + bw] = gt * fre[e];
        si[r*65 + bw] = gt * fim[e];
    }
    fft64_2d(sr, si, tid, 512, -1.f);
    for (int e = tid; e < 4096; e += 512) {
        float re = sr[(e>>6)*65 + (e&63)], im = si[(e>>6)*65 + (e&63)];
        float v = sqrtf(re*re + im*im) * (1.f/4096.f)
                + x[((size_t)b*HW_ + e)*C_ + (256 + c)];
        g_out2[((size_t)(b*512 + 256 + c))*HW_ + e] = v;
    }
}

// ---------------- final projection via tf32 mma ----------------
__global__ void proj_mma_kernel(const float* __restrict__ pw, const float* __restrict__ pb,
                                float* __restrict__ out) {
    __shared__ uint32_t xs[128][20];
    __shared__ uint32_t ws[128][20];
    int b = blockIdx.z, nt = blockIdx.y, ot = blockIdx.x;
    int tid = threadIdx.x, lane = tid & 31, warp = tid >> 5;
    int wm = warp & 3, wn = warp >> 2;
    int g = lane >> 2, t = lane & 3;
    float acc[2][8][4];
#pragma unroll
    for (int i = 0; i < 2; i++)
#pragma unroll
        for (int j = 0; j < 8; j++)
#pragma unroll
            for (int q = 0; q < 4; q++) acc[i][j][q] = 0.f;

    int n0g = nt*128, o0g = ot*128;
    for (int kc = 0; kc < 512; kc += 16) {
        __syncthreads();
#pragma unroll
        for (int r = 0; r < 2; r++) {
            int e = tid + r*256;
            int k = e >> 5, n4 = e & 31;
            float4 v = *(const float4*)&g_out2[((size_t)(b*512 + kc + k))*HW_ + n0g + n4*4];
            xs[n4*4+0][k] = f2tf(v.x);
            xs[n4*4+1][k] = f2tf(v.y);
            xs[n4*4+2][k] = f2tf(v.z);
            xs[n4*4+3][k] = f2tf(v.w);
        }
#pragma unroll
        for (int r = 0; r < 2; r++) {
            int e = tid + r*256;
            int o = e >> 2, ch = e & 3;
            float4 v = *(const float4*)&pw[(size_t)(o0g + o)*512 + kc + ch*4];
            uint4 u = make_uint4(f2tf(v.x), f2tf(v.y), f2tf(v.z), f2tf(v.w));
            *(uint4*)&ws[o][ch*4] = u;
        }
        __syncthreads();
#pragma unroll
        for (int ks = 0; ks < 16; ks += 8) {
            int kr = ks + t;
            uint32_t a[2][4];
#pragma unroll
            for (int mi = 0; mi < 2; mi++) {
                int m0 = wm*32 + mi*16 + g;
                a[mi][0] = xs[m0][kr];
                a[mi][1] = xs[m0+8][kr];
                a[mi][2] = xs[m0][kr+4];
                a[mi][3] = xs[m0+8][kr+4];
            }
#pragma unroll
            for (int ni = 0; ni < 8; ni++) {
                int n0 = wn*64 + ni*8 + g;
                uint32_t b0 = ws[n0][kr];
                uint32_t b1 = ws[n0][kr+4];
                mma8(acc[0][ni], a[0], b0, b1);
                mma8(acc[1][ni], a[1], b0, b1);
            }
        }
    }
#pragma unroll
    for (int mi = 0; mi < 2; mi++) {
#pragma unroll
        for (int half = 0; half < 2; half++) {
            int n = n0g + wm*32 + mi*16 + g + half*8;
#pragma unroll
            for (int ni = 0; ni < 8; ni++) {
                int o = o0g + wn*64 + ni*8 + 2*t;
                float2 bias = *(const float2*)&pb[o];
                float v0 = acc[mi][ni][half*2+0] + bias.x;
                float v1 = acc[mi][ni][half*2+1] + bias.y;
                *(float2*)&out[((size_t)b*HW_ + n)*C_ + o] = make_float2(v0, v1);
            }
        }
    }
}

// ---------------- launch ----------------
extern "C" void kernel_launch(void* const* d_in, const int* in_sizes, int n_in,
                              void* d_out, int out_size) {
    const float* x       = (const float*)d_in[0];
    const float* conv2_w = (const float*)d_in[1];
    const float* conv2_b = (const float*)d_in[2];
    const float* bn2_g   = (const float*)d_in[3];
    const float* bn2_b   = (const float*)d_in[4];
    const float* bn2_m   = (const float*)d_in[5];
    const float* bn2_v   = (const float*)d_in[6];
    const float* temp    = (const float*)d_in[7];
    const float* w1_w    = (const float*)d_in[8];
    const float* w1_b    = (const float*)d_in[9];
    const float* bnw_g   = (const float*)d_in[10];
    const float* bnw_b   = (const float*)d_in[11];
    const float* bnw_m   = (const float*)d_in[12];
    const float* bnw_v   = (const float*)d_in[13];
    const float* w2_w    = (const float*)d_in[14];
    const float* w2_b    = (const float*)d_in[15];
    const float* proj_w  = (const float*)d_in[16];
    const float* proj_b  = (const float*)d_in[17];
    float* out = (float*)d_out;

    prep_kernel<<<1024, 256>>>(conv2_w);
    conv_mma_kernel<<<dim3(2, 32, 8), 256>>>(x, conv2_b, bn2_g, bn2_b, bn2_m, bn2_v);
    fft2_fwd_kernel<<<2048, 512>>>();
    attn_gemm64_kernel<<<dim3(64, KSPLIT), 256>>>();
    attn_fin_kernel<<<64, 256>>>(temp);
    attn_apply_kernel<<<dim3(32, 64), 256>>>();
    ifft_row_kernel<<<2048, 512>>>(x);
    g1_kernel<<<dim3(16, 8), 256>>>(w1_w, w1_b, bnw_g, bnw_b, bnw_m, bnw_v);
    ifft2_gate_kernel<<<2048, 512>>>(x, w2_w, w2_b);
    proj_mma_kernel<<<dim3(4, 32, 8), 256>>>(proj_w, proj_b, out);
}

// round 6
// speedup vs baseline: 2.8343x; 1.0284x over previous
#include <cuda_runtime.h>
#include <math.h>
#include <stdint.h>

#define B_  8
#define C_  512
#define DD_ 256
#define HW_ 4096
#define HEADS_ 8
#define CPH_ 32
#define HID_ 16
#define KSPLIT 8

// ---------------- scratch (static device globals; no allocation) ----------------
__device__ float  g_wt[9*256*512];          // conv weights [tap][co][cin]
__device__ float2 g_twid[4096];             // e^{-2*pi*i*k/4096}, FULL circle
__device__ float  g_y   [(size_t)B_*DD_*HW_];   // conv+bn+relu output
__device__ float  g_fre [(size_t)B_*DD_*HW_];   // fft2 real
__device__ float  g_fim [(size_t)B_*DD_*HW_];   // fft2 imag
__device__ float  g_g1  [(size_t)B_*HID_*HW_];
__device__ float  g_attnS[KSPLIT*64*64*64]; // partial S [kq][bh][64][64]
__device__ float2 g_attn2[64*1024];         // softmaxed + ifft32-folded attn
__device__ float  g_or  [(size_t)B_*DD_*HW_];   // attn_apply out re
__device__ float  g_oi  [(size_t)B_*DD_*HW_];   // attn_apply out im
__device__ float  g_out2[(size_t)B_*C_*HW_];    // concat(out_f2,out_l2)+x2d

// ---------------- tf32 helpers ----------------
__device__ __forceinline__ uint32_t f2tf(float f) {
    uint32_t u;
    asm("cvt.rna.tf32.f32 %0, %1;" : "=r"(u) : "f"(f));
    return u;
}
__device__ __forceinline__ void mma8(float c[4], const uint32_t a[4], uint32_t b0, uint32_t b1) {
    asm volatile("mma.sync.aligned.m16n8k8.row.col.f32.tf32.tf32.f32 "
        "{%0,%1,%2,%3}, {%4,%5,%6,%7}, {%8,%9}, {%0,%1,%2,%3};"
        : "+f"(c[0]), "+f"(c[1]), "+f"(c[2]), "+f"(c[3])
        : "r"(a[0]), "r"(a[1]), "r"(a[2]), "r"(a[3]), "r"(b0), "r"(b1));
}

// base-4 digit reversal helpers
__device__ __forceinline__ int dig4_6(int x) {          // 6 bits (64)
    int b = __brev(x) >> 26;
    return ((b & 0x15) << 1) | ((b >> 1) & 0x15);
}
__device__ __forceinline__ int dig4_12(int x) {         // 12 bits (4096)
    int b = __brev(x) >> 20;
    return ((b & 0x555) << 1) | ((b >> 1) & 0x555);
}

// ---------------- prep ----------------
__global__ void prep_kernel(const float* __restrict__ cw) {
    int tid = blockIdx.x*blockDim.x + threadIdx.x;
    int stride = gridDim.x*blockDim.x;
    if (tid < 4096) {
        float s, c;
        sincosf(-6.28318530717958647692f * (float)tid / 4096.f, &s, &c);
        g_twid[tid] = make_float2(c, s);
    }
    for (int e = tid; e < 9*256*512; e += stride) {
        int tap = e / (256*512);
        int rem = e - tap*256*512;
        int co = rem >> 9;
        int cin = rem & 511;
        g_wt[e] = cw[(co*512 + cin)*9 + tap];
    }
}

// ---------------- conv via tf32 mma: 128co x 128pos tiles, KC=32 ----------------
__global__ void conv_mma_kernel(const float* __restrict__ x, const float* __restrict__ cb,
                                const float* __restrict__ bg, const float* __restrict__ bb,
                                const float* __restrict__ bm, const float* __restrict__ bv) {
    __shared__ uint32_t xs[128][36];
    __shared__ uint32_t ws[128][36];
    int b = blockIdx.z, pt = blockIdx.y, ct = blockIdx.x;
    int tid = threadIdx.x, lane = tid & 31, warp = tid >> 5;
    int wm = warp & 3, wn = warp >> 2;
    int g = lane >> 2, t = lane & 3;
    float acc[2][8][4];
#pragma unroll
    for (int i = 0; i < 2; i++)
#pragma unroll
        for (int j = 0; j < 8; j++)
#pragma unroll
            for (int q = 0; q < 4; q++) acc[i][j][q] = 0.f;

    int pos0 = pt*128;
    for (int tap = 0; tap < 9; tap++) {
        int dh = 3*((tap/3) - 1), dw = 3*((tap%3) - 1);
        const float* wtp = g_wt + ((size_t)tap*256 + ct*128)*512;
        for (int kc = 0; kc < 512; kc += 32) {
            __syncthreads();
#pragma unroll
            for (int r = 0; r < 4; r++) {
                int e = tid + r*256;
                int pos = e >> 3, ch = e & 7;
                int gp = pos0 + pos;
                int ih = (gp >> 6) + dh, iw = (gp & 63) + dw;
                float4 v = make_float4(0.f, 0.f, 0.f, 0.f);
                if ((unsigned)ih < 64u && (unsigned)iw < 64u)
                    v = *(const float4*)&x[((size_t)(b*HW_) + ih*64 + iw)*C_ + kc + ch*4];
                uint4 u = make_uint4(f2tf(v.x), f2tf(v.y), f2tf(v.z), f2tf(v.w));
                *(uint4*)&xs[pos][ch*4] = u;
            }
#pragma unroll
            for (int r = 0; r < 4; r++) {
                int e = tid + r*256;
                int co = e >> 3, ch = e & 7;
                float4 v = *(const float4*)&wtp[(size_t)co*512 + kc + ch*4];
                uint4 u = make_uint4(f2tf(v.x), f2tf(v.y), f2tf(v.z), f2tf(v.w));
                *(uint4*)&ws[co][ch*4] = u;
            }
            __syncthreads();
#pragma unroll
            for (int ks = 0; ks < 32; ks += 8) {
                int kr = ks + t;
                uint32_t a[2][4];
#pragma unroll
                for (int mi = 0; mi < 2; mi++) {
                    int m0 = wm*32 + mi*16 + g;
                    a[mi][0] = ws[m0][kr];
                    a[mi][1] = ws[m0+8][kr];
                    a[mi][2] = ws[m0][kr+4];
                    a[mi][3] = ws[m0+8][kr+4];
                }
#pragma unroll
                for (int ni = 0; ni < 8; ni++) {
                    int n0 = wn*64 + ni*8 + g;
                    uint32_t b0 = xs[n0][kr];
                    uint32_t b1 = xs[n0][kr+4];
                    mma8(acc[0][ni], a[0], b0, b1);
                    mma8(acc[1][ni], a[1], b0, b1);
                }
            }
        }
    }
#pragma unroll
    for (int mi = 0; mi < 2; mi++) {
#pragma unroll
        for (int half = 0; half < 2; half++) {
            int o = ct*128 + wm*32 + mi*16 + g + half*8;
            float s = bg[o] * rsqrtf(bv[o] + 1e-5f);
            float t0 = cb[o]*s + bb[o] - bm[o]*s;
            float* dst = g_y + ((size_t)(b*DD_ + o))*HW_;
#pragma unroll
            for (int ni = 0; ni < 8; ni++) {
                int pos = pos0 + wn*64 + ni*8 + 2*t;
                float v0 = fmaxf(acc[mi][ni][half*2+0]*s + t0, 0.f);
                float v1 = fmaxf(acc[mi][ni][half*2+1]*s + t0, 0.f);
                *(float2*)&dst[pos] = make_float2(v0, v1);
            }
        }
    }
}

// ---------------- 64x64 2D FFT core, RADIX-4 (3+3 stages) ----------------
// input must be loaded with cols digit4-reversed; output natural order.
__device__ __forceinline__ void fft64_2d_r4(float* sr, float* si, int tid, int nt, float sign) {
    // row pass (along cols, stride 1)
#pragma unroll
    for (int s = 0; s < 3; s++) {
        int L = 1 << (2*s);
        int stp = 1024 >> (2*s);
        __syncthreads();
        for (int t = tid; t < 1024; t += nt) {
            int row = t >> 4, q = t & 15;
            int j = q & (L-1);
            int grp = q >> (2*s);
            int base = row*65 + grp*(L<<2) + j;
            float2 w1 = g_twid[j*stp];
            float2 w2 = g_twid[2*j*stp];
            float2 w3 = g_twid[3*j*stp];
            float w1i = sign*w1.y, w2i = sign*w2.y, w3i = sign*w3.y;
            float ar = sr[base],       ai = si[base];
            float x1r = sr[base+L],    x1i = si[base+L];
            float x2r = sr[base+2*L],  x2i = si[base+2*L];
            float x3r = sr[base+3*L],  x3i = si[base+3*L];
            float br = x1r*w1.x - x1i*w1i, bi = x1r*w1i + x1i*w1.x;
            float cr = x2r*w2.x - x2i*w2i, ci = x2r*w2i + x2i*w2.x;
            float dr = x3r*w3.x - x3i*w3i, di = x3r*w3i + x3i*w3.x;
            float t0r = ar+cr, t0i = ai+ci;
            float t1r = ar-cr, t1i = ai-ci;
            float t2r = br+dr, t2i = bi+di;
            float t3r = br-dr, t3i = bi-di;
            sr[base]     = t0r+t2r;        si[base]     = t0i+t2i;
            sr[base+2*L] = t0r-t2r;        si[base+2*L] = t0i-t2i;
            sr[base+L]   = t1r + sign*t3i; si[base+L]   = t1i - sign*t3r;
            sr[base+3*L] = t1r - sign*t3i; si[base+3*L] = t1i + sign*t3r;
        }
    }
    // digit4-reverse permute rows for column pass
    __syncthreads();
    for (int e = tid; e < 4096; e += nt) {
        int r = e >> 6, cc = e & 63;
        int d4 = dig4_6(r);
        if (r < d4) {
            float a = sr[r*65+cc]; sr[r*65+cc] = sr[d4*65+cc]; sr[d4*65+cc] = a;
            float b = si[r*65+cc]; si[r*65+cc] = si[d4*65+cc]; si[d4*65+cc] = b;
        }
    }
    // column pass (stride 65)
#pragma unroll
    for (int s = 0; s < 3; s++) {
        int L = 1 << (2*s);
        int stp = 1024 >> (2*s);
        __syncthreads();
        for (int t = tid; t < 1024; t += nt) {
            int col = t & 63, q = t >> 6;
            int j = q & (L-1);
            int grp = q >> (2*s);
            int base = (grp*(L<<2) + j)*65 + col;
            int LL = L*65;
            float2 w1 = g_twid[j*stp];
            float2 w2 = g_twid[2*j*stp];
            float2 w3 = g_twid[3*j*stp];
            float w1i = sign*w1.y, w2i = sign*w2.y, w3i = sign*w3.y;
            float ar = sr[base],       ai = si[base];
            float x1r = sr[base+LL],   x1i = si[base+LL];
            float x2r = sr[base+2*LL], x2i = si[base+2*LL];
            float x3r = sr[base+3*LL], x3i = si[base+3*LL];
            float br = x1r*w1.x - x1i*w1i, bi = x1r*w1i + x1i*w1.x;
            float cr = x2r*w2.x - x2i*w2i, ci = x2r*w2i + x2i*w2.x;
            float dr = x3r*w3.x - x3i*w3i, di = x3r*w3i + x3i*w3.x;
            float t0r = ar+cr, t0i = ai+ci;
            float t1r = ar-cr, t1i = ai-ci;
            float t2r = br+dr, t2i = bi+di;
            float t3r = br-dr, t3i = bi-di;
            sr[base]      = t0r+t2r;        si[base]      = t0i+t2i;
            sr[base+2*LL] = t0r-t2r;        si[base+2*LL] = t0i-t2i;
            sr[base+LL]   = t1r + sign*t3i; si[base+LL]   = t1i - sign*t3r;
            sr[base+3*LL] = t1r - sign*t3i; si[base+3*LL] = t1i + sign*t3r;
        }
    }
    __syncthreads();
}

__global__ void fft2_fwd_kernel() {
    __shared__ float sr[64*65], si[64*65];
    int bc = blockIdx.x;
    int tid = threadIdx.x;
    const float* src = g_y + (size_t)bc*HW_;
    for (int e = tid; e < 4096; e += 512) {
        int r = e >> 6, w = e & 63;
        sr[r*65 + dig4_6(w)] = src[e];
        si[r*65 + dig4_6(w)] = 0.f;
    }
    fft64_2d_r4(sr, si, tid, 512, 1.f);
    float* dr = g_fre + (size_t)bc*HW_;
    float* di = g_fim + (size_t)bc*HW_;
    for (int e = tid; e < 4096; e += 512) {
        dr[e] = sr[(e>>6)*65 + (e&63)];
        di[e] = si[(e>>6)*65 + (e&63)];
    }
}

// ---------------- attention scores: partial S = G G^T over k-slice ----------------
__global__ void attn_gemm64_kernel() {
    __shared__ uint32_t gs[64][36];
    int bh = blockIdx.x, kq = blockIdx.y;
    int tid = threadIdx.x, lane = tid & 31, warp = tid >> 5;
    int wm = warp & 3, wn = warp >> 2;
    int g = lane >> 2, t = lane & 3;
    float acc[4][4];
#pragma unroll
    for (int i = 0; i < 4; i++)
#pragma unroll
        for (int q = 0; q < 4; q++) acc[i][q] = 0.f;
    const float* fr = g_fre + (size_t)bh*CPH_*HW_;
    const float* fi = g_fim + (size_t)bh*CPH_*HW_;
    int kbeg = kq*(HW_/KSPLIT), kend = kbeg + HW_/KSPLIT;
    for (int k0 = kbeg; k0 < kend; k0 += 32) {
        __syncthreads();
#pragma unroll
        for (int r = 0; r < 2; r++) {
            int e = tid + r*256;
            int row = e >> 3, kqq = e & 7;
            const float* src = (row < 32) ? (fr + (size_t)row*HW_) : (fi + (size_t)(row-32)*HW_);
            float4 v = *(const float4*)&src[k0 + kqq*4];
            uint4 u = make_uint4(f2tf(v.x), f2tf(v.y), f2tf(v.z), f2tf(v.w));
            *(uint4*)&gs[row][kqq*4] = u;
        }
        __syncthreads();
#pragma unroll
        for (int ks = 0; ks < 32; ks += 8) {
            int kr = ks + t;
            uint32_t a[4];
            a[0] = gs[wm*16+g][kr];
            a[1] = gs[wm*16+g+8][kr];
            a[2] = gs[wm*16+g][kr+4];
            a[3] = gs[wm*16+g+8][kr+4];
#pragma unroll
            for (int ni = 0; ni < 4; ni++) {
                int n0 = wn*32 + ni*8 + g;
                mma8(acc[ni], a, gs[n0][kr], gs[n0][kr+4]);
            }
        }
    }
    float* S = g_attnS + ((size_t)(kq*64 + bh))*4096;
#pragma unroll
    for (int ni = 0; ni < 4; ni++) {
        int d = wn*32 + ni*8 + 2*t;
        int c0 = wm*16 + g;
        *(float2*)&S[(size_t)c0*64 + d]     = make_float2(acc[ni][0], acc[ni][1]);
        *(float2*)&S[(size_t)(c0+8)*64 + d] = make_float2(acc[ni][2], acc[ni][3]);
    }
}

// ---------------- attn finalize ----------------
__global__ void attn_fin_kernel(const float* __restrict__ temp) {
    int bh = blockIdx.x;
    int head = bh & 7;
    int tid = threadIdx.x;
    __shared__ float Ss[4096];
    __shared__ float ar_[32*33], ai_[32*33];
    __shared__ float inv[32];
    for (int p = tid; p < 4096; p += 256) {
        float s = 0.f;
#pragma unroll
        for (int q = 0; q < KSPLIT; q++)
            s += g_attnS[((size_t)(q*64 + bh))*4096 + p];
        Ss[p] = s;
    }
    __syncthreads();
    if (tid < 32)
        inv[tid] = rsqrtf(fmaxf(Ss[tid*64 + tid] + Ss[(32+tid)*64 + 32+tid], 1e-24f));
    __syncthreads();
    float tmp = temp[head];
    for (int p = tid; p < 1024; p += 256) {
        int cc = p >> 5, dd = p & 31;
        float sre = Ss[cc*64 + dd] - Ss[(32+cc)*64 + (32+dd)];
        float sim = Ss[cc*64 + (32+dd)] + Ss[(32+cc)*64 + dd];
        float sc = inv[cc] * inv[dd] * tmp;
        ar_[cc*33+dd] = sre*sc;
        ai_[cc*33+dd] = sim*sc;
    }
    __syncthreads();
    int w = tid >> 5, lane = tid & 31;
    for (int r = w; r < 32; r += 8) {
        float vr = ar_[r*33+lane];
        float m = vr;
        for (int o = 16; o; o >>= 1) m = fmaxf(m, __shfl_xor_sync(0xffffffffu, m, o));
        float e = expf(vr - m); float s = e;
        for (int o = 16; o; o >>= 1) s += __shfl_xor_sync(0xffffffffu, s, o);
        ar_[r*33+lane] = e / s;
        float vi = ai_[r*33+lane];
        m = vi;
        for (int o = 16; o; o >>= 1) m = fmaxf(m, __shfl_xor_sync(0xffffffffu, m, o));
        e = expf(vi - m); s = e;
        for (int o = 16; o; o >>= 1) s += __shfl_xor_sync(0xffffffffu, s, o);
        ai_[r*33+lane] = e / s;
    }
    __syncthreads();
    for (int p = tid; p < 1024; p += 256) {
        int k = p >> 5, dd = p & 31;
        float accr = 0.f, acci = 0.f;
#pragma unroll
        for (int cc = 0; cc < 32; cc++) {
            float2 w2 = g_twid[((k*cc) & 31) * 128];
            float wr = w2.x, wi = -w2.y;
            float xr = ar_[cc*33+dd], xi = ai_[cc*33+dd];
            accr += wr*xr - wi*xi;
            acci += wr*xi + wi*xr;
        }
        g_attn2[(size_t)bh*1024 + p] = make_float2(accr*(1.f/32.f), acci*(1.f/32.f));
    }
}

// ---------------- attn apply ----------------
__global__ void attn_apply_kernel() {
    __shared__ float sfr[32][132], sfi[32][132];
    __shared__ float2 a2s[32][32];
    int nc = blockIdx.x, bh = blockIdx.y;
    int tid = threadIdx.x;
    for (int p = tid; p < 1024; p += 256)
        a2s[p>>5][p&31] = g_attn2[(size_t)bh*1024 + p];
    const float* fr = g_fre + (size_t)bh*CPH_*HW_ + nc*128;
    const float* fi = g_fim + (size_t)bh*CPH_*HW_ + nc*128;
    for (int e = tid; e < 1024; e += 256) {
        int d = e >> 5, j = e & 31;
        *(float4*)&sfr[d][j*4] = *(const float4*)&fr[(size_t)d*HW_ + j*4];
        *(float4*)&sfi[d][j*4] = *(const float4*)&fi[(size_t)d*HW_ + j*4];
    }
    __syncthreads();
    int tx = tid & 15, ty = tid >> 4;
    int k0 = ty*2, n0 = tx*8;
    float ar0[8], ai0[8], ar1[8], ai1[8];
#pragma unroll
    for (int j = 0; j < 8; j++) { ar0[j]=0.f; ai0[j]=0.f; ar1[j]=0.f; ai1[j]=0.f; }
#pragma unroll
    for (int d = 0; d < 32; d++) {
        float2 a0 = a2s[k0][d], a1 = a2s[k0+1][d];
        float4 f0 = *(float4*)&sfr[d][n0], f1 = *(float4*)&sfr[d][n0+4];
        float4 h0 = *(float4*)&sfi[d][n0], h1 = *(float4*)&sfi[d][n0+4];
        float frv[8] = {f0.x,f0.y,f0.z,f0.w,f1.x,f1.y,f1.z,f1.w};
        float fiv[8] = {h0.x,h0.y,h0.z,h0.w,h1.x,h1.y,h1.z,h1.w};
#pragma unroll
        for (int j = 0; j < 8; j++) {
            ar0[j] += a0.x*frv[j] - a0.y*fiv[j];
            ai0[j] += a0.x*fiv[j] + a0.y*frv[j];
            ar1[j] += a1.x*frv[j] - a1.y*fiv[j];
            ai1[j] += a1.x*fiv[j] + a1.y*frv[j];
        }
    }
    size_t base0 = ((size_t)(bh*32 + k0))*HW_ + nc*128 + n0;
    size_t base1 = base0 + HW_;
    *(float4*)&g_or[base0]   = make_float4(ar0[0],ar0[1],ar0[2],ar0[3]);
    *(float4*)&g_or[base0+4] = make_float4(ar0[4],ar0[5],ar0[6],ar0[7]);
    *(float4*)&g_oi[base0]   = make_float4(ai0[0],ai0[1],ai0[2],ai0[3]);
    *(float4*)&g_oi[base0+4] = make_float4(ai0[4],ai0[5],ai0[6],ai0[7]);
    *(float4*)&g_or[base1]   = make_float4(ar1[0],ar1[1],ar1[2],ar1[3]);
    *(float4*)&g_or[base1+4] = make_float4(ar1[4],ar1[5],ar1[6],ar1[7]);
    *(float4*)&g_oi[base1]   = make_float4(ai1[0],ai1[1],ai1[2],ai1[3]);
    *(float4*)&g_oi[base1+4] = make_float4(ai1[4],ai1[5],ai1[6],ai1[7]);
}

// ---------------- row ifft4096 RADIX-4 + abs + residual (512 threads) -------------
#define SKW(i) ((i) + ((i) >> 7))
__global__ void ifft_row_kernel(const float* __restrict__ x) {
    __shared__ float sr[4128], si[4128];
    int gid = blockIdx.x;
    int b = gid >> 8, cg = gid & 255;
    int tid = threadIdx.x;
    const float* pr = g_or + (size_t)gid*HW_;
    const float* pi = g_oi + (size_t)gid*HW_;
    for (int nn = tid; nn < 4096; nn += 512) {
        int d = SKW(dig4_12(nn));
        sr[d] = pr[nn];
        si[d] = pi[nn];
    }
#pragma unroll
    for (int s = 0; s < 6; s++) {
        int L = 1 << (2*s);
        int stp = 1024 >> (2*s);
        __syncthreads();
        for (int t = tid; t < 1024; t += 512) {
            int j = t & (L-1);
            int grp = t >> (2*s);
            int base = grp*(L<<2) + j;
            int i0 = SKW(base), i1 = SKW(base+L), i2 = SKW(base+2*L), i3 = SKW(base+3*L);
            float2 w1 = g_twid[j*stp];
            float2 w2 = g_twid[2*j*stp];
            float2 w3 = g_twid[3*j*stp];
            // inverse: conj twiddles (sign = -1)
            float ar = sr[i0],  ai = si[i0];
            float x1r = sr[i1], x1i = si[i1];
            float x2r = sr[i2], x2i = si[i2];
            float x3r = sr[i3], x3i = si[i3];
            float br = x1r*w1.x + x1i*w1.y, bi = -x1r*w1.y + x1i*w1.x;
            float cr = x2r*w2.x + x2i*w2.y, ci = -x2r*w2.y + x2i*w2.x;
            float dr = x3r*w3.x + x3i*w3.y, di = -x3r*w3.y + x3i*w3.x;
            float t0r = ar+cr, t0i = ai+ci;
            float t1r = ar-cr, t1i = ai-ci;
            float t2r = br+dr, t2i = bi+di;
            float t3r = br-dr, t3i = bi-di;
            sr[i0] = t0r+t2r;  si[i0] = t0i+t2i;
            sr[i2] = t0r-t2r;  si[i2] = t0i-t2i;
            sr[i1] = t1r - t3i; si[i1] = t1i + t3r;   // sign=-1
            sr[i3] = t1r + t3i; si[i3] = t1i - t3r;
        }
    }
    __syncthreads();
    for (int nn = tid; nn < 4096; nn += 512) {
        float re = sr[SKW(nn)], im = si[SKW(nn)];
        float v = sqrtf(re*re + im*im) * (1.f/4096.f)
                + x[((size_t)b*HW_ + nn)*C_ + cg];
        g_out2[((size_t)(b*512) + cg)*HW_ + nn] = v;
    }
}

// ---------------- gating MLP stage 1 ----------------
__global__ void g1_kernel(const float* __restrict__ w1w, const float* __restrict__ w1b,
                          const float* __restrict__ bg, const float* __restrict__ bb,
                          const float* __restrict__ bm, const float* __restrict__ bv) {
    __shared__ float sw[HID_*DD_];
    __shared__ float sa[HID_], st[HID_];
    int b = blockIdx.y;
    int tid = threadIdx.x;
    int n = blockIdx.x*256 + tid;
    for (int e = tid; e < HID_*DD_; e += 256) sw[e] = w1w[e];
    if (tid < HID_) {
        float s = bg[tid] * rsqrtf(bv[tid] + 1e-5f);
        sa[tid] = s;
        st[tid] = w1b[tid]*s + bb[tid] - bm[tid]*s;
    }
    __syncthreads();
    float acc[HID_];
#pragma unroll
    for (int o = 0; o < HID_; o++) acc[o] = 0.f;
    const float* fr = g_fre + (size_t)b*DD_*HW_ + n;
    for (int c = 0; c < DD_; c++) {
        float v = fr[(size_t)c*HW_];
#pragma unroll
        for (int o = 0; o < HID_; o++) acc[o] += v * sw[o*DD_ + c];
    }
#pragma unroll
    for (int o = 0; o < HID_; o++)
        g_g1[((size_t)(b*HID_ + o))*HW_ + n] = fmaxf(acc[o]*sa[o] + st[o], 0.f);
}

// ---------------- fused gate + ifft2 + abs + residual (512 threads) ---------------
__global__ void ifft2_gate_kernel(const float* __restrict__ x,
                                  const float* __restrict__ w2w,
                                  const float* __restrict__ w2b) {
    __shared__ float sr[64*65], si[64*65];
    __shared__ float w2s[HID_];
    int bc = blockIdx.x;
    int b = bc >> 8, c = bc & 255;
    int tid = threadIdx.x;
    if (tid < HID_) w2s[tid] = w2w[c*HID_ + tid];
    __syncthreads();
    float bias = w2b[c];
    float acc[8];
#pragma unroll
    for (int j = 0; j < 8; j++) acc[j] = bias;
    const float* g1p = g_g1 + (size_t)b*HID_*HW_;
#pragma unroll
    for (int o = 0; o < HID_; o++) {
        float w = w2s[o];
        const float* row = g1p + (size_t)o*HW_;
#pragma unroll
        for (int j = 0; j < 8; j++) acc[j] += w * row[tid + j*512];
    }
    const float* fre = g_fre + (size_t)bc*HW_;
    const float* fim = g_fim + (size_t)bc*HW_;
#pragma unroll
    for (int j = 0; j < 8; j++) {
        int e = tid + j*512;
        float gt = 1.f / (1.f + expf(-acc[j]));
        int r = e >> 6, w = e & 63;
        int dw = dig4_6(w);
        sr[r*65 + dw] = gt * fre[e];
        si[r*65 + dw] = gt * fim[e];
    }
    fft64_2d_r4(sr, si, tid, 512, -1.f);
    for (int e = tid; e < 4096; e += 512) {
        float re = sr[(e>>6)*65 + (e&63)], im = si[(e>>6)*65 + (e&63)];
        float v = sqrtf(re*re + im*im) * (1.f/4096.f)
                + x[((size_t)b*HW_ + e)*C_ + (256 + c)];
        g_out2[((size_t)(b*512 + 256 + c))*HW_ + e] = v;
    }
}

// ---------------- final projection via tf32 mma, KC=32 ----------------
__global__ void proj_mma_kernel(const float* __restrict__ pw, const float* __restrict__ pb,
                                float* __restrict__ out) {
    __shared__ uint32_t xs[128][36];
    __shared__ uint32_t ws[128][36];
    int b = blockIdx.z, nt = blockIdx.y, ot = blockIdx.x;
    int tid = threadIdx.x, lane = tid & 31, warp = tid >> 5;
    int wm = warp & 3, wn = warp >> 2;
    int g = lane >> 2, t = lane & 3;
    float acc[2][8][4];
#pragma unroll
    for (int i = 0; i < 2; i++)
#pragma unroll
        for (int j = 0; j < 8; j++)
#pragma unroll
            for (int q = 0; q < 4; q++) acc[i][j][q] = 0.f;

    int n0g = nt*128, o0g = ot*128;
    for (int kc = 0; kc < 512; kc += 32) {
        __syncthreads();
#pragma unroll
        for (int r = 0; r < 4; r++) {
            int e = tid + r*256;
            int k = e >> 5, n4 = e & 31;
            float4 v = *(const float4*)&g_out2[((size_t)(b*512 + kc + k))*HW_ + n0g + n4*4];
            xs[n4*4+0][k] = f2tf(v.x);
            xs[n4*4+1][k] = f2tf(v.y);
            xs[n4*4+2][k] = f2tf(v.z);
            xs[n4*4+3][k] = f2tf(v.w);
        }
#pragma unroll
        for (int r = 0; r < 4; r++) {
            int e = tid + r*256;
            int o = e >> 3, ch = e & 7;
            float4 v = *(const float4*)&pw[(size_t)(o0g + o)*512 + kc + ch*4];
            uint4 u = make_uint4(f2tf(v.x), f2tf(v.y), f2tf(v.z), f2tf(v.w));
            *(uint4*)&ws[o][ch*4] = u;
        }
        __syncthreads();
#pragma unroll
        for (int ks = 0; ks < 32; ks += 8) {
            int kr = ks + t;
            uint32_t a[2][4];
#pragma unroll
            for (int mi = 0; mi < 2; mi++) {
                int m0 = wm*32 + mi*16 + g;
                a[mi][0] = xs[m0][kr];
                a[mi][1] = xs[m0+8][kr];
                a[mi][2] = xs[m0][kr+4];
                a[mi][3] = xs[m0+8][kr+4];
            }
#pragma unroll
            for (int ni = 0; ni < 8; ni++) {
                int n0 = wn*64 + ni*8 + g;
                uint32_t b0 = ws[n0][kr];
                uint32_t b1 = ws[n0][kr+4];
                mma8(acc[0][ni], a[0], b0, b1);
                mma8(acc[1][ni], a[1], b0, b1);
            }
        }
    }
#pragma unroll
    for (int mi = 0; mi < 2; mi++) {
#pragma unroll
        for (int half = 0; half < 2; half++) {
            int n = n0g + wm*32 + mi*16 + g + half*8;
#pragma unroll
            for (int ni = 0; ni < 8; ni++) {
                int o = o0g + wn*64 + ni*8 + 2*t;
                float2 bias = *(const float2*)&pb[o];
                float v0 = acc[mi][ni][half*2+0] + bias.x;
                float v1 = acc[mi][ni][half*2+1] + bias.y;
                *(float2*)&out[((size_t)b*HW_ + n)*C_ + o] = make_float2(v0, v1);
            }
        }
    }
}

// ---------------- launch ----------------
extern "C" void kernel_launch(void* const* d_in, const int* in_sizes, int n_in,
                              void* d_out, int out_size) {
    const float* x       = (const float*)d_in[0];
    const float* conv2_w = (const float*)d_in[1];
    const float* conv2_b = (const float*)d_in[2];
    const float* bn2_g   = (const float*)d_in[3];
    const float* bn2_b   = (const float*)d_in[4];
    const float* bn2_m   = (const float*)d_in[5];
    const float* bn2_v   = (const float*)d_in[6];
    const float* temp    = (const float*)d_in[7];
    const float* w1_w    = (const float*)d_in[8];
    const float* w1_b    = (const float*)d_in[9];
    const float* bnw_g   = (const float*)d_in[10];
    const float* bnw_b   = (const float*)d_in[11];
    const float* bnw_m   = (const float*)d_in[12];
    const float* bnw_v   = (const float*)d_in[13];
    const float* w2_w    = (const float*)d_in[14];
    const float* w2_b    = (const float*)d_in[15];
    const float* proj_w  = (const float*)d_in[16];
    const float* proj_b  = (const float*)d_in[17];
    float* out = (float*)d_out;

    prep_kernel<<<1024, 256>>>(conv2_w);
    conv_mma_kernel<<<dim3(2, 32, 8), 256>>>(x, conv2_b, bn2_g, bn2_b, bn2_m, bn2_v);
    fft2_fwd_kernel<<<2048, 512>>>();
    attn_gemm64_kernel<<<dim3(64, KSPLIT), 256>>>();
    attn_fin_kernel<<<64, 256>>>(temp);
    attn_apply_kernel<<<dim3(32, 64), 256>>>();
    ifft_row_kernel<<<2048, 512>>>(x);
    g1_kernel<<<dim3(16, 8), 256>>>(w1_w, w1_b, bnw_g, bnw_b, bnw_m, bnw_v);
    ifft2_gate_kernel<<<2048, 512>>>(x, w2_w, w2_b);
    proj_mma_kernel<<<dim3(4, 32, 8), 256>>>(proj_w, proj_b, out);
}